// round 9
// baseline (speedup 1.0000x reference)
#include <cuda_runtime.h>
#include <cuda_fp16.h>
#include <cstdint>

// CausalAttention B=8, S=2048, D=1024 fp32 via fp16 2-term mma.sync GEMMs.
//   A = Ah + Al (two fp16), B ~= Bh (one fp16).
//   Hi term: fp32-accum mma. Lo (correction) term: fp16-accum mma (folded into
//   fp32 acc in epilogue) — tests the 2x fp16-accum HMMA rate hypothesis and
//   breaks the accumulator RAW chain between hi and lo MMAs.

constexpr int B_ = 8;
constexpr int S_ = 2048;
constexpr int D_ = 1024;
constexpr int MTOT = B_ * S_;          // 16384

// ---------------- scratch (device globals; allocation-free) ----------------
__device__ __half g_xh[MTOT * D_], g_xl[MTOT * D_];
__device__ __half g_Wth[3][D_ * D_];                     // W^T hi only [3][D,D]
__device__ __half g_Qh[MTOT * D_], g_Ql[MTOT * D_];      // Q 2-term (A side)
__device__ __half g_Kh[MTOT * D_];                       // K hi only (B side)
__device__ __half g_Vh[MTOT * D_];                       // V hi only
__device__ __half g_Vth[MTOT * D_];                      // V^T hi [B][D][S]
__device__ float  g_Sc[(size_t)B_ * S_ * S_];
__device__ __half g_Ph[(size_t)B_ * S_ * S_], g_Pl[(size_t)B_ * S_ * S_];

// ---------------- helpers ----------------
__device__ __forceinline__ uint32_t smem_u32(const void* p) {
    uint32_t a;
    asm("{ .reg .u64 t; cvta.to.shared.u64 t, %1; cvt.u32.u64 %0, t; }"
        : "=r"(a) : "l"(p));
    return a;
}
__device__ __forceinline__ void cp_async16(uint32_t dst, const void* src) {
    asm volatile("cp.async.cg.shared.global [%0], [%1], 16;"
                 :: "r"(dst), "l"(__cvta_generic_to_global(src)) : "memory");
}
__device__ __forceinline__ void cp_commit() {
    asm volatile("cp.async.commit_group;" ::: "memory");
}
template <int N>
__device__ __forceinline__ void cp_wait() {
    asm volatile("cp.async.wait_group %0;" :: "n"(N) : "memory");
}
__device__ __forceinline__ void ldm_x4(uint32_t* r, uint32_t addr) {
    asm volatile("ldmatrix.sync.aligned.m8n8.x4.shared.b16 {%0,%1,%2,%3}, [%4];"
                 : "=r"(r[0]), "=r"(r[1]), "=r"(r[2]), "=r"(r[3]) : "r"(addr));
}
// fp32-accumulate f16 mma
__device__ __forceinline__ void mma16816(float* c, const uint32_t* a,
                                         uint32_t b0, uint32_t b1) {
    asm volatile(
        "mma.sync.aligned.m16n8k16.row.col.f32.f16.f16.f32 "
        "{%0,%1,%2,%3}, {%4,%5,%6,%7}, {%8,%9}, {%0,%1,%2,%3};"
        : "+f"(c[0]), "+f"(c[1]), "+f"(c[2]), "+f"(c[3])
        : "r"(a[0]), "r"(a[1]), "r"(a[2]), "r"(a[3]), "r"(b0), "r"(b1));
}
// fp16-accumulate f16 mma (for the lo-correction term)
__device__ __forceinline__ void mma16816h(uint32_t* c, const uint32_t* a,
                                          uint32_t b0, uint32_t b1) {
    asm volatile(
        "mma.sync.aligned.m16n8k16.row.col.f16.f16.f16.f16 "
        "{%0,%1}, {%2,%3,%4,%5}, {%6,%7}, {%0,%1};"
        : "+r"(c[0]), "+r"(c[1])
        : "r"(a[0]), "r"(a[1]), "r"(a[2]), "r"(a[3]), "r"(b0), "r"(b1));
}

// ---------------- split / transpose / softmax kernels ----------------
__global__ __launch_bounds__(256)
void split_f32h(const float* __restrict__ in, __half* __restrict__ h,
                __half* __restrict__ l, int n4) {
    int i = blockIdx.x * 256 + threadIdx.x;
    if (i >= n4) return;
    float4 v = *reinterpret_cast<const float4*>(in + (size_t)i * 4);
    __half h0 = __float2half_rn(v.x), h1 = __float2half_rn(v.y);
    __half h2 = __float2half_rn(v.z), h3 = __float2half_rn(v.w);
    __half2 hp0{h0, h1}, hp1{h2, h3};
    __half2 lp0 = __floats2half2_rn(v.x - __half2float(h0), v.y - __half2float(h1));
    __half2 lp1 = __floats2half2_rn(v.z - __half2float(h2), v.w - __half2float(h3));
    uint2 hu, lu;
    hu.x = *reinterpret_cast<uint32_t*>(&hp0); hu.y = *reinterpret_cast<uint32_t*>(&hp1);
    lu.x = *reinterpret_cast<uint32_t*>(&lp0); lu.y = *reinterpret_cast<uint32_t*>(&lp1);
    *reinterpret_cast<uint2*>(h + (size_t)i * 4) = hu;
    *reinterpret_cast<uint2*>(l + (size_t)i * 4) = lu;
}

__global__ __launch_bounds__(256)
void transpose_h(const float* __restrict__ in, __half* __restrict__ oh, int R, int C) {
    __shared__ float t[32][33];
    int c0 = blockIdx.x * 32, r0 = blockIdx.y * 32;
    int tx = threadIdx.x;
#pragma unroll
    for (int j = 0; j < 4; j++) {
        int ty = threadIdx.y * 4 + j;
        t[ty][tx] = in[(size_t)(r0 + ty) * C + c0 + tx];
    }
    __syncthreads();
#pragma unroll
    for (int j = 0; j < 4; j++) {
        int ty = threadIdx.y * 4 + j;
        oh[(size_t)(c0 + ty) * R + r0 + tx] = __float2half_rn(t[tx][ty]);
    }
}

__global__ __launch_bounds__(256)
void transpose_half(const __half* __restrict__ ih, __half* __restrict__ oh) {
    __shared__ __half th[32][34];
    int z = blockIdx.z;
    ih += (size_t)z * S_ * D_;
    oh += (size_t)z * D_ * S_;
    int c0 = blockIdx.x * 32, r0 = blockIdx.y * 32;
    int tx = threadIdx.x;
#pragma unroll
    for (int j = 0; j < 4; j++) {
        int ty = threadIdx.y * 4 + j;
        th[ty][tx] = ih[(size_t)(r0 + ty) * D_ + c0 + tx];
    }
    __syncthreads();
#pragma unroll
    for (int j = 0; j < 4; j++) {
        int ty = threadIdx.y * 4 + j;
        oh[(size_t)(c0 + ty) * S_ + r0 + tx] = th[tx][ty];
    }
}

__global__ __launch_bounds__(256)
void softmax_split(const float* __restrict__ Sc, __half* __restrict__ Ph,
                   __half* __restrict__ Pl) {
    const int r = blockIdx.x, i = r % S_;
    const size_t off = (size_t)r * S_;
    const float* row = Sc + off;
    const int n = i + 1;
    const int nIt = (n + 255) >> 8;
    const int kLim = (n + 127) & ~127;
    const float scale = 0.03125f;                // 1/sqrt(1024)
    const int tid = threadIdx.x;

    float vals[8];
    float m = -INFINITY;
    for (int it = 0; it < nIt; it++) {
        int j = it * 256 + tid;
        float v = (j < n) ? row[j] * scale : -INFINITY;
        vals[it] = v; m = fmaxf(m, v);
    }
    __shared__ float red[8];
#pragma unroll
    for (int o = 16; o > 0; o >>= 1) m = fmaxf(m, __shfl_xor_sync(~0u, m, o));
    if ((tid & 31) == 0) red[tid >> 5] = m;
    __syncthreads();
    float M = red[0];
#pragma unroll
    for (int w = 1; w < 8; w++) M = fmaxf(M, red[w]);
    __syncthreads();
    float ssum = 0.f;
    for (int it = 0; it < nIt; it++) {
        int j = it * 256 + tid;
        float e = (j < n) ? __expf(vals[it] - M) : 0.f;
        vals[it] = e; ssum += e;
    }
#pragma unroll
    for (int o = 16; o > 0; o >>= 1) ssum += __shfl_xor_sync(~0u, ssum, o);
    if ((tid & 31) == 0) red[tid >> 5] = ssum;
    __syncthreads();
    float T = 0.f;
#pragma unroll
    for (int w = 0; w < 8; w++) T += red[w];
    const float inv = 1.f / T;
    for (int it = 0; it < nIt; it++) {
        int j = it * 256 + tid;
        if (j < kLim) {
            float v = (j < n) ? vals[it] * inv : 0.f;
            __half hv = __float2half_rn(v);
            Ph[off + j] = hv;
            Pl[off + j] = __float2half_rn(v - __half2float(hv));
        }
    }
}

// ---------------- fp16 2-term HMMA GEMM (f16-accum lo term) ----------------
// C[M,N] = (Ah+Al)[M,K] * Bh[N,K]^T, tile 128x128, BK=64, 8 warps (32x64).
// Hi term -> fp32 acc; lo term -> fp16 acc, merged in epilogue.
// EP: 0 -> fp32 to Cf;  1 -> fp16 hi+lo (Ch,Cl);  2 -> fp16 hi only (Ch).
constexpr int TILE_B = 16384;                    // one 128x64 fp16 tile
constexpr int STG_BYTES = 3 * TILE_B;            // Ah,Al,Bh = 48 KB
constexpr int SMEM_BYTES = 2 * STG_BYTES;        // 96 KB

template <int EP, bool CSKIP, bool CLIMK>
__global__ __launch_bounds__(256, 1)
void hmma_gemm(const __half* __restrict__ Ah, const __half* __restrict__ Al,
               const __half* __restrict__ Bh,
               float* __restrict__ Cf, __half* __restrict__ Ch,
               __half* __restrict__ Cl,
               int N, int K, size_t sA, size_t sB, size_t sC)
{
    const int rowBase = blockIdx.y * 128, colBase = blockIdx.x * 128;
    if (CSKIP && colBase > rowBase) return;
    const int kEnd = CLIMK ? (rowBase + 128) : K;
    const int NC = kEnd >> 6;                     // chunks of 64 K

    extern __shared__ char smem[];
    const uint32_t sbase = smem_u32(smem);

    const size_t zA = (size_t)blockIdx.z * sA, zB = (size_t)blockIdx.z * sB;
    Ah += zA; Al += zA; Bh += zB;

    const int tid = threadIdx.x, wid = tid >> 5, lid = tid & 31;
    const int wr = wid & 3, wc = wid >> 2;         // warp grid 4(m) x 2(n)

    uint32_t aRel[2], aXor[2];
#pragma unroll
    for (int mt = 0; mt < 2; mt++) {
        int r = wr * 32 + mt * 16 + (lid & 15);
        aRel[mt] = r * 128;
        aXor[mt] = (r & 7) << 4;
    }
    const uint32_t aHalf = (lid >> 4) * 16;
    const int g = lid >> 3;
    uint32_t bRel[4], bXor[4];
#pragma unroll
    for (int nt = 0; nt < 4; nt++) {
        int r = wc * 64 + nt * 16 + ((g & 1) << 3) + (lid & 7);
        bRel[nt] = r * 128;
        bXor[nt] = (r & 7) << 4;
    }
    const uint32_t bHalf = (g >> 1) * 16;

    float acc[2][8][4];
    uint32_t accl[2][8][2];                       // fp16 lo-correction acc
#pragma unroll
    for (int i = 0; i < 2; i++)
#pragma unroll
        for (int j = 0; j < 8; j++) {
#pragma unroll
            for (int k = 0; k < 4; k++) acc[i][j][k] = 0.f;
            accl[i][j][0] = 0u; accl[i][j][1] = 0u;
        }

    auto loadChunk = [&](int c, int buf) {
        const int k0 = c << 6;
        const uint32_t st = sbase + buf * STG_BYTES;
#pragma unroll
        for (int j = 0; j < 4; j++) {
            int idx = j * 256 + tid;                   // 0..1023
            int row = idx >> 3, col = idx & 7;         // 128 rows x 8 cols of 16B
            uint32_t off = row * 128 + ((col * 16) ^ ((row & 7) << 4));
            size_t ga = (size_t)(rowBase + row) * K + k0 + col * 8;
            size_t gb = (size_t)(colBase + row) * K + k0 + col * 8;
            cp_async16(st + off,              Ah + ga);
            cp_async16(st + TILE_B + off,     Al + ga);
            cp_async16(st + 2 * TILE_B + off, Bh + gb);
        }
        cp_commit();
    };

    loadChunk(0, 0);

    for (int c = 0; c < NC; c++) {
        const int buf = c & 1;
        cp_wait<0>();
        __syncthreads();
        if (c + 1 < NC) loadChunk(c + 1, buf ^ 1);

        const uint32_t sAh = sbase + buf * STG_BYTES;
        const uint32_t sAl = sAh + TILE_B;
        const uint32_t sBh = sAh + 2 * TILE_B;
#pragma unroll
        for (int ks = 0; ks < 4; ks++) {
            const uint32_t kb = ks * 32;
            uint32_t ah[2][4], al[2][4], bh[4][4];
#pragma unroll
            for (int nt = 0; nt < 4; nt++)
                ldm_x4(bh[nt], sBh + bRel[nt] + ((kb + bHalf) ^ bXor[nt]));
#pragma unroll
            for (int mt = 0; mt < 2; mt++) {
                uint32_t o = aRel[mt] + ((kb + aHalf) ^ aXor[mt]);
                ldm_x4(ah[mt], sAh + o);
                ldm_x4(al[mt], sAl + o);
            }
#pragma unroll
            for (int mt = 0; mt < 2; mt++)
#pragma unroll
                for (int nt = 0; nt < 4; nt++) {
                    mma16816(acc[mt][2 * nt],     ah[mt], bh[nt][0], bh[nt][2]);
                    mma16816(acc[mt][2 * nt + 1], ah[mt], bh[nt][1], bh[nt][3]);
                    mma16816h(accl[mt][2 * nt],     al[mt], bh[nt][0], bh[nt][2]);
                    mma16816h(accl[mt][2 * nt + 1], al[mt], bh[nt][1], bh[nt][3]);
                }
        }
        __syncthreads();
    }

    // ---- epilogue: merge fp16 lo acc into fp32 acc, then store ----
    const int colW = colBase + wc * 64 + (lid & 3) * 2;
#pragma unroll
    for (int mt = 0; mt < 2; mt++) {
        const int row0 = rowBase + wr * 32 + mt * 16 + (lid >> 2);
#pragma unroll
        for (int nt = 0; nt < 8; nt++) {
            const int col = colW + nt * 8;
            float* cc = acc[mt][nt];
            __half2 l0 = *reinterpret_cast<__half2*>(&accl[mt][nt][0]);
            __half2 l1 = *reinterpret_cast<__half2*>(&accl[mt][nt][1]);
            float m0 = cc[0] + __half2float(l0.x);
            float m1 = cc[1] + __half2float(l0.y);
            float m2 = cc[2] + __half2float(l1.x);
            float m3 = cc[3] + __half2float(l1.y);
            if (EP == 0) {
                float* base = Cf + (size_t)blockIdx.z * sC;
                *reinterpret_cast<float2*>(base + (size_t)row0 * N + col) =
                    make_float2(m0, m1);
                *reinterpret_cast<float2*>(base + (size_t)(row0 + 8) * N + col) =
                    make_float2(m2, m3);
            } else {
                float mv[4] = {m0, m1, m2, m3};
#pragma unroll
                for (int h = 0; h < 2; h++) {
                    float f0 = mv[2 * h], f1 = mv[2 * h + 1];
                    __half h0 = __float2half_rn(f0), h1 = __float2half_rn(f1);
                    __half2 hp{h0, h1};
                    size_t o = (size_t)(row0 + h * 8) * N + col;
                    *reinterpret_cast<uint32_t*>(Ch + o) =
                        *reinterpret_cast<uint32_t*>(&hp);
                    if (EP == 1) {
                        __half2 lp = __floats2half2_rn(f0 - __half2float(h0),
                                                       f1 - __half2float(h1));
                        *reinterpret_cast<uint32_t*>(Cl + o) =
                            *reinterpret_cast<uint32_t*>(&lp);
                    }
                }
            }
        }
    }
}

// ---------------- launch ----------------
extern "C" void kernel_launch(void* const* d_in, const int* in_sizes, int n_in,
                              void* d_out, int out_size)
{
    const float* x  = (const float*)d_in[0];
    const float* Wq = (const float*)d_in[1];
    const float* Wk = (const float*)d_in[2];
    const float* Wv = (const float*)d_in[3];
    float* out = (float*)d_out;

    __half *xh, *xl, *Wth, *Qh, *Ql, *Kh, *Vh, *Vth, *Ph, *Pl;
    float *Sc;
    cudaGetSymbolAddress((void**)&xh, g_xh);   cudaGetSymbolAddress((void**)&xl, g_xl);
    cudaGetSymbolAddress((void**)&Wth, g_Wth);
    cudaGetSymbolAddress((void**)&Qh, g_Qh);   cudaGetSymbolAddress((void**)&Ql, g_Ql);
    cudaGetSymbolAddress((void**)&Kh, g_Kh);   cudaGetSymbolAddress((void**)&Vh, g_Vh);
    cudaGetSymbolAddress((void**)&Vth, g_Vth);
    cudaGetSymbolAddress((void**)&Sc, g_Sc);
    cudaGetSymbolAddress((void**)&Ph, g_Ph);   cudaGetSymbolAddress((void**)&Pl, g_Pl);

    cudaFuncSetAttribute(hmma_gemm<1, false, false>,
                         cudaFuncAttributeMaxDynamicSharedMemorySize, SMEM_BYTES);
    cudaFuncSetAttribute(hmma_gemm<2, false, false>,
                         cudaFuncAttributeMaxDynamicSharedMemorySize, SMEM_BYTES);
    cudaFuncSetAttribute(hmma_gemm<0, true, false>,
                         cudaFuncAttributeMaxDynamicSharedMemorySize, SMEM_BYTES);
    cudaFuncSetAttribute(hmma_gemm<0, false, true>,
                         cudaFuncAttributeMaxDynamicSharedMemorySize, SMEM_BYTES);

    // 1. split x into fp16 hi/lo
    split_f32h<<<(MTOT * D_ / 4 + 255) / 256, 256>>>(x, xh, xl, MTOT * D_ / 4);
    // 2. transpose weights -> fp16 hi only [dout, din]
    dim3 tb(32, 8);
    transpose_h<<<dim3(32, 32, 1), tb>>>(Wq, Wth, D_, D_);
    transpose_h<<<dim3(32, 32, 1), tb>>>(Wk, Wth + (size_t)D_ * D_, D_, D_);
    transpose_h<<<dim3(32, 32, 1), tb>>>(Wv, Wth + 2 * (size_t)D_ * D_, D_, D_);

    // 3. projections: Q needs hi+lo (A side of QK); K,V need hi only (B sides)
    dim3 gp(D_ / 128, MTOT / 128, 1);
    hmma_gemm<1, false, false><<<gp, 256, SMEM_BYTES>>>(
        xh, xl, Wth, nullptr, Qh, Ql, D_, D_, 0, 0, 0);
    hmma_gemm<2, false, false><<<gp, 256, SMEM_BYTES>>>(
        xh, xl, Wth + (size_t)D_ * D_, nullptr, Kh, nullptr, D_, D_, 0, 0, 0);
    hmma_gemm<2, false, false><<<gp, 256, SMEM_BYTES>>>(
        xh, xl, Wth + 2 * (size_t)D_ * D_, nullptr, Vh, nullptr, D_, D_, 0, 0, 0);

    // 4. V -> Vt (fp16, per batch [S,D] -> [D,S])
    transpose_half<<<dim3(D_ / 32, S_ / 32, B_), tb>>>(Vh, Vth);

    // 5. scores = Q K^T (lower-triangular blocks), fp32
    hmma_gemm<0, true, false><<<dim3(S_ / 128, S_ / 128, B_), 256, SMEM_BYTES>>>(
        Qh, Ql, Kh, Sc, nullptr, nullptr, S_, D_,
        (size_t)S_ * D_, (size_t)S_ * D_, (size_t)S_ * S_);

    // 6. causal-limited softmax -> split fp16 P
    softmax_split<<<B_ * S_, 256>>>(Sc, Ph, Pl);

    // 7. out = P V  (K limited to rowBase+128)
    hmma_gemm<0, false, true><<<dim3(D_ / 128, S_ / 128, B_), 256, SMEM_BYTES>>>(
        Ph, Pl, Vth, out, nullptr, nullptr, D_, S_,
        (size_t)S_ * S_, (size_t)D_ * S_, (size_t)S_ * D_);
}

// round 10
// speedup vs baseline: 1.0751x; 1.0751x over previous
#include <cuda_runtime.h>
#include <cuda_fp16.h>
#include <cstdint>

// CausalAttention B=8, S=2048, D=1024 fp32 via fp16 2-term mma.sync GEMMs.
//   A = Ah + Al (two fp16, exact to 22 bits), B ~= Bh (one fp16).
//   C = Ah*Bh + Al*Bh = A*Bh in fp32 accum — error is only B's fp16 rounding.
// R10 = R8 + MMA scheduling fix: hi-group then lo-group (RAW distance 2 -> 16),
//       non-volatile mma asm so ptxas can pipeline.

constexpr int B_ = 8;
constexpr int S_ = 2048;
constexpr int D_ = 1024;
constexpr int MTOT = B_ * S_;          // 16384

// ---------------- scratch (device globals; allocation-free) ----------------
__device__ __half g_xh[MTOT * D_], g_xl[MTOT * D_];
__device__ __half g_Wth[3][D_ * D_];                     // W^T hi only [3][D,D]
__device__ __half g_Qh[MTOT * D_], g_Ql[MTOT * D_];      // Q 2-term (A side)
__device__ __half g_Kh[MTOT * D_];                       // K hi only (B side)
__device__ __half g_Vh[MTOT * D_];                       // V hi only
__device__ __half g_Vth[MTOT * D_];                      // V^T hi [B][D][S]
__device__ float  g_Sc[(size_t)B_ * S_ * S_];
__device__ __half g_Ph[(size_t)B_ * S_ * S_], g_Pl[(size_t)B_ * S_ * S_];

// ---------------- helpers ----------------
__device__ __forceinline__ uint32_t smem_u32(const void* p) {
    uint32_t a;
    asm("{ .reg .u64 t; cvta.to.shared.u64 t, %1; cvt.u32.u64 %0, t; }"
        : "=r"(a) : "l"(p));
    return a;
}
__device__ __forceinline__ void cp_async16(uint32_t dst, const void* src) {
    asm volatile("cp.async.cg.shared.global [%0], [%1], 16;"
                 :: "r"(dst), "l"(__cvta_generic_to_global(src)) : "memory");
}
__device__ __forceinline__ void cp_commit() {
    asm volatile("cp.async.commit_group;" ::: "memory");
}
template <int N>
__device__ __forceinline__ void cp_wait() {
    asm volatile("cp.async.wait_group %0;" :: "n"(N) : "memory");
}
__device__ __forceinline__ void ldm_x4(uint32_t* r, uint32_t addr) {
    asm volatile("ldmatrix.sync.aligned.m8n8.x4.shared.b16 {%0,%1,%2,%3}, [%4];"
                 : "=r"(r[0]), "=r"(r[1]), "=r"(r[2]), "=r"(r[3]) : "r"(addr));
}
// fp32-accumulate f16 mma — NON-volatile: pure register op, lets ptxas schedule
__device__ __forceinline__ void mma16816(float* c, const uint32_t* a,
                                         uint32_t b0, uint32_t b1) {
    asm("mma.sync.aligned.m16n8k16.row.col.f32.f16.f16.f32 "
        "{%0,%1,%2,%3}, {%4,%5,%6,%7}, {%8,%9}, {%0,%1,%2,%3};"
        : "+f"(c[0]), "+f"(c[1]), "+f"(c[2]), "+f"(c[3])
        : "r"(a[0]), "r"(a[1]), "r"(a[2]), "r"(a[3]), "r"(b0), "r"(b1));
}

// ---------------- split / transpose / softmax kernels ----------------
__global__ __launch_bounds__(256)
void split_f32h(const float* __restrict__ in, __half* __restrict__ h,
                __half* __restrict__ l, int n4) {
    int i = blockIdx.x * 256 + threadIdx.x;
    if (i >= n4) return;
    float4 v = *reinterpret_cast<const float4*>(in + (size_t)i * 4);
    __half h0 = __float2half_rn(v.x), h1 = __float2half_rn(v.y);
    __half h2 = __float2half_rn(v.z), h3 = __float2half_rn(v.w);
    __half2 hp0{h0, h1}, hp1{h2, h3};
    __half2 lp0 = __floats2half2_rn(v.x - __half2float(h0), v.y - __half2float(h1));
    __half2 lp1 = __floats2half2_rn(v.z - __half2float(h2), v.w - __half2float(h3));
    uint2 hu, lu;
    hu.x = *reinterpret_cast<uint32_t*>(&hp0); hu.y = *reinterpret_cast<uint32_t*>(&hp1);
    lu.x = *reinterpret_cast<uint32_t*>(&lp0); lu.y = *reinterpret_cast<uint32_t*>(&lp1);
    *reinterpret_cast<uint2*>(h + (size_t)i * 4) = hu;
    *reinterpret_cast<uint2*>(l + (size_t)i * 4) = lu;
}

__global__ __launch_bounds__(256)
void transpose_h(const float* __restrict__ in, __half* __restrict__ oh, int R, int C) {
    __shared__ float t[32][33];
    int c0 = blockIdx.x * 32, r0 = blockIdx.y * 32;
    int tx = threadIdx.x;
#pragma unroll
    for (int j = 0; j < 4; j++) {
        int ty = threadIdx.y * 4 + j;
        t[ty][tx] = in[(size_t)(r0 + ty) * C + c0 + tx];
    }
    __syncthreads();
#pragma unroll
    for (int j = 0; j < 4; j++) {
        int ty = threadIdx.y * 4 + j;
        oh[(size_t)(c0 + ty) * R + r0 + tx] = __float2half_rn(t[tx][ty]);
    }
}

__global__ __launch_bounds__(256)
void transpose_half(const __half* __restrict__ ih, __half* __restrict__ oh) {
    __shared__ __half th[32][34];
    int z = blockIdx.z;
    ih += (size_t)z * S_ * D_;
    oh += (size_t)z * D_ * S_;
    int c0 = blockIdx.x * 32, r0 = blockIdx.y * 32;
    int tx = threadIdx.x;
#pragma unroll
    for (int j = 0; j < 4; j++) {
        int ty = threadIdx.y * 4 + j;
        th[ty][tx] = ih[(size_t)(r0 + ty) * D_ + c0 + tx];
    }
    __syncthreads();
#pragma unroll
    for (int j = 0; j < 4; j++) {
        int ty = threadIdx.y * 4 + j;
        oh[(size_t)(c0 + ty) * S_ + r0 + tx] = th[tx][ty];
    }
}

__global__ __launch_bounds__(256)
void softmax_split(const float* __restrict__ Sc, __half* __restrict__ Ph,
                   __half* __restrict__ Pl) {
    const int r = blockIdx.x, i = r % S_;
    const size_t off = (size_t)r * S_;
    const float* row = Sc + off;
    const int n = i + 1;
    const int nIt = (n + 255) >> 8;
    const int kLim = (n + 127) & ~127;
    const float scale = 0.03125f;                // 1/sqrt(1024)
    const int tid = threadIdx.x;

    float vals[8];
    float m = -INFINITY;
    for (int it = 0; it < nIt; it++) {
        int j = it * 256 + tid;
        float v = (j < n) ? row[j] * scale : -INFINITY;
        vals[it] = v; m = fmaxf(m, v);
    }
    __shared__ float red[8];
#pragma unroll
    for (int o = 16; o > 0; o >>= 1) m = fmaxf(m, __shfl_xor_sync(~0u, m, o));
    if ((tid & 31) == 0) red[tid >> 5] = m;
    __syncthreads();
    float M = red[0];
#pragma unroll
    for (int w = 1; w < 8; w++) M = fmaxf(M, red[w]);
    __syncthreads();
    float ssum = 0.f;
    for (int it = 0; it < nIt; it++) {
        int j = it * 256 + tid;
        float e = (j < n) ? __expf(vals[it] - M) : 0.f;
        vals[it] = e; ssum += e;
    }
#pragma unroll
    for (int o = 16; o > 0; o >>= 1) ssum += __shfl_xor_sync(~0u, ssum, o);
    if ((tid & 31) == 0) red[tid >> 5] = ssum;
    __syncthreads();
    float T = 0.f;
#pragma unroll
    for (int w = 0; w < 8; w++) T += red[w];
    const float inv = 1.f / T;
    for (int it = 0; it < nIt; it++) {
        int j = it * 256 + tid;
        if (j < kLim) {
            float v = (j < n) ? vals[it] * inv : 0.f;
            __half hv = __float2half_rn(v);
            Ph[off + j] = hv;
            Pl[off + j] = __float2half_rn(v - __half2float(hv));
        }
    }
}

// ---------------- fp16 2-term HMMA GEMM ----------------
// C[M,N] = (Ah+Al)[M,K] * Bh[N,K]^T, tile 128x128, BK=64, 8 warps (32x64).
// Per ks-step: 16 hi mmas (independent accs), then 16 lo mmas — RAW distance 16.
// EP: 0 -> fp32 to Cf;  1 -> fp16 hi+lo (Ch,Cl);  2 -> fp16 hi only (Ch).
constexpr int TILE_B = 16384;                    // one 128x64 fp16 tile
constexpr int STG_BYTES = 3 * TILE_B;            // Ah,Al,Bh = 48 KB
constexpr int SMEM_BYTES = 2 * STG_BYTES;        // 96 KB

template <int EP, bool CSKIP, bool CLIMK>
__global__ __launch_bounds__(256, 2)
void hmma_gemm(const __half* __restrict__ Ah, const __half* __restrict__ Al,
               const __half* __restrict__ Bh,
               float* __restrict__ Cf, __half* __restrict__ Ch,
               __half* __restrict__ Cl,
               int N, int K, size_t sA, size_t sB, size_t sC)
{
    const int rowBase = blockIdx.y * 128, colBase = blockIdx.x * 128;
    if (CSKIP && colBase > rowBase) return;
    const int kEnd = CLIMK ? (rowBase + 128) : K;
    const int NC = kEnd >> 6;                     // chunks of 64 K

    extern __shared__ char smem[];
    const uint32_t sbase = smem_u32(smem);

    const size_t zA = (size_t)blockIdx.z * sA, zB = (size_t)blockIdx.z * sB;
    Ah += zA; Al += zA; Bh += zB;

    const int tid = threadIdx.x, wid = tid >> 5, lid = tid & 31;
    const int wr = wid & 3, wc = wid >> 2;         // warp grid 4(m) x 2(n)

    uint32_t aRel[2], aXor[2];
#pragma unroll
    for (int mt = 0; mt < 2; mt++) {
        int r = wr * 32 + mt * 16 + (lid & 15);
        aRel[mt] = r * 128;
        aXor[mt] = (r & 7) << 4;
    }
    const uint32_t aHalf = (lid >> 4) * 16;
    const int g = lid >> 3;
    uint32_t bRel[4], bXor[4];
#pragma unroll
    for (int nt = 0; nt < 4; nt++) {
        int r = wc * 64 + nt * 16 + ((g & 1) << 3) + (lid & 7);
        bRel[nt] = r * 128;
        bXor[nt] = (r & 7) << 4;
    }
    const uint32_t bHalf = (g >> 1) * 16;

    float acc[2][8][4];
#pragma unroll
    for (int i = 0; i < 2; i++)
#pragma unroll
        for (int j = 0; j < 8; j++)
#pragma unroll
            for (int k = 0; k < 4; k++) acc[i][j][k] = 0.f;

    auto loadChunk = [&](int c, int buf) {
        const int k0 = c << 6;
        const uint32_t st = sbase + buf * STG_BYTES;
#pragma unroll
        for (int j = 0; j < 4; j++) {
            int idx = j * 256 + tid;                   // 0..1023
            int row = idx >> 3, col = idx & 7;         // 128 rows x 8 cols of 16B
            uint32_t off = row * 128 + ((col * 16) ^ ((row & 7) << 4));
            size_t ga = (size_t)(rowBase + row) * K + k0 + col * 8;
            size_t gb = (size_t)(colBase + row) * K + k0 + col * 8;
            cp_async16(st + off,              Ah + ga);
            cp_async16(st + TILE_B + off,     Al + ga);
            cp_async16(st + 2 * TILE_B + off, Bh + gb);
        }
        cp_commit();
    };

    loadChunk(0, 0);

    for (int c = 0; c < NC; c++) {
        const int buf = c & 1;
        cp_wait<0>();
        __syncthreads();
        if (c + 1 < NC) loadChunk(c + 1, buf ^ 1);

        const uint32_t sAh = sbase + buf * STG_BYTES;
        const uint32_t sAl = sAh + TILE_B;
        const uint32_t sBh = sAh + 2 * TILE_B;
#pragma unroll
        for (int ks = 0; ks < 4; ks++) {
            const uint32_t kb = ks * 32;
            uint32_t ah[2][4], al[2][4], bh[4][4];
#pragma unroll
            for (int nt = 0; nt < 4; nt++)
                ldm_x4(bh[nt], sBh + bRel[nt] + ((kb + bHalf) ^ bXor[nt]));
#pragma unroll
            for (int mt = 0; mt < 2; mt++) {
                uint32_t o = aRel[mt] + ((kb + aHalf) ^ aXor[mt]);
                ldm_x4(ah[mt], sAh + o);
                ldm_x4(al[mt], sAl + o);
            }
            // hi group: 16 mmas across 16 distinct acc quads (no RAW)
#pragma unroll
            for (int mt = 0; mt < 2; mt++)
#pragma unroll
                for (int nt = 0; nt < 4; nt++) {
                    mma16816(acc[mt][2 * nt],     ah[mt], bh[nt][0], bh[nt][2]);
                    mma16816(acc[mt][2 * nt + 1], ah[mt], bh[nt][1], bh[nt][3]);
                }
            // lo group: same accs revisited 16 mmas later — latency covered
#pragma unroll
            for (int mt = 0; mt < 2; mt++)
#pragma unroll
                for (int nt = 0; nt < 4; nt++) {
                    mma16816(acc[mt][2 * nt],     al[mt], bh[nt][0], bh[nt][2]);
                    mma16816(acc[mt][2 * nt + 1], al[mt], bh[nt][1], bh[nt][3]);
                }
        }
        __syncthreads();
    }

    // ---- epilogue ----
    const int colW = colBase + wc * 64 + (lid & 3) * 2;
#pragma unroll
    for (int mt = 0; mt < 2; mt++) {
        const int row0 = rowBase + wr * 32 + mt * 16 + (lid >> 2);
#pragma unroll
        for (int nt = 0; nt < 8; nt++) {
            const int col = colW + nt * 8;
            const float* cc = acc[mt][nt];
            if (EP == 0) {
                float* base = Cf + (size_t)blockIdx.z * sC;
                *reinterpret_cast<float2*>(base + (size_t)row0 * N + col) =
                    make_float2(cc[0], cc[1]);
                *reinterpret_cast<float2*>(base + (size_t)(row0 + 8) * N + col) =
                    make_float2(cc[2], cc[3]);
            } else {
#pragma unroll
                for (int h = 0; h < 2; h++) {
                    float f0 = cc[2 * h], f1 = cc[2 * h + 1];
                    __half h0 = __float2half_rn(f0), h1 = __float2half_rn(f1);
                    __half2 hp{h0, h1};
                    size_t o = (size_t)(row0 + h * 8) * N + col;
                    *reinterpret_cast<uint32_t*>(Ch + o) =
                        *reinterpret_cast<uint32_t*>(&hp);
                    if (EP == 1) {
                        __half2 lp = __floats2half2_rn(f0 - __half2float(h0),
                                                       f1 - __half2float(h1));
                        *reinterpret_cast<uint32_t*>(Cl + o) =
                            *reinterpret_cast<uint32_t*>(&lp);
                    }
                }
            }
        }
    }
}

// ---------------- launch ----------------
extern "C" void kernel_launch(void* const* d_in, const int* in_sizes, int n_in,
                              void* d_out, int out_size)
{
    const float* x  = (const float*)d_in[0];
    const float* Wq = (const float*)d_in[1];
    const float* Wk = (const float*)d_in[2];
    const float* Wv = (const float*)d_in[3];
    float* out = (float*)d_out;

    __half *xh, *xl, *Wth, *Qh, *Ql, *Kh, *Vh, *Vth, *Ph, *Pl;
    float *Sc;
    cudaGetSymbolAddress((void**)&xh, g_xh);   cudaGetSymbolAddress((void**)&xl, g_xl);
    cudaGetSymbolAddress((void**)&Wth, g_Wth);
    cudaGetSymbolAddress((void**)&Qh, g_Qh);   cudaGetSymbolAddress((void**)&Ql, g_Ql);
    cudaGetSymbolAddress((void**)&Kh, g_Kh);   cudaGetSymbolAddress((void**)&Vh, g_Vh);
    cudaGetSymbolAddress((void**)&Vth, g_Vth);
    cudaGetSymbolAddress((void**)&Sc, g_Sc);
    cudaGetSymbolAddress((void**)&Ph, g_Ph);   cudaGetSymbolAddress((void**)&Pl, g_Pl);

    cudaFuncSetAttribute(hmma_gemm<1, false, false>,
                         cudaFuncAttributeMaxDynamicSharedMemorySize, SMEM_BYTES);
    cudaFuncSetAttribute(hmma_gemm<2, false, false>,
                         cudaFuncAttributeMaxDynamicSharedMemorySize, SMEM_BYTES);
    cudaFuncSetAttribute(hmma_gemm<0, true, false>,
                         cudaFuncAttributeMaxDynamicSharedMemorySize, SMEM_BYTES);
    cudaFuncSetAttribute(hmma_gemm<0, false, true>,
                         cudaFuncAttributeMaxDynamicSharedMemorySize, SMEM_BYTES);

    // 1. split x into fp16 hi/lo
    split_f32h<<<(MTOT * D_ / 4 + 255) / 256, 256>>>(x, xh, xl, MTOT * D_ / 4);
    // 2. transpose weights -> fp16 hi only [dout, din]
    dim3 tb(32, 8);
    transpose_h<<<dim3(32, 32, 1), tb>>>(Wq, Wth, D_, D_);
    transpose_h<<<dim3(32, 32, 1), tb>>>(Wk, Wth + (size_t)D_ * D_, D_, D_);
    transpose_h<<<dim3(32, 32, 1), tb>>>(Wv, Wth + 2 * (size_t)D_ * D_, D_, D_);

    // 3. projections: Q needs hi+lo (A side of QK); K,V need hi only (B sides)
    dim3 gp(D_ / 128, MTOT / 128, 1);
    hmma_gemm<1, false, false><<<gp, 256, SMEM_BYTES>>>(
        xh, xl, Wth, nullptr, Qh, Ql, D_, D_, 0, 0, 0);
    hmma_gemm<2, false, false><<<gp, 256, SMEM_BYTES>>>(
        xh, xl, Wth + (size_t)D_ * D_, nullptr, Kh, nullptr, D_, D_, 0, 0, 0);
    hmma_gemm<2, false, false><<<gp, 256, SMEM_BYTES>>>(
        xh, xl, Wth + 2 * (size_t)D_ * D_, nullptr, Vh, nullptr, D_, D_, 0, 0, 0);

    // 4. V -> Vt (fp16, per batch [S,D] -> [D,S])
    transpose_half<<<dim3(D_ / 32, S_ / 32, B_), tb>>>(Vh, Vth);

    // 5. scores = Q K^T (lower-triangular blocks), fp32
    hmma_gemm<0, true, false><<<dim3(S_ / 128, S_ / 128, B_), 256, SMEM_BYTES>>>(
        Qh, Ql, Kh, Sc, nullptr, nullptr, S_, D_,
        (size_t)S_ * D_, (size_t)S_ * D_, (size_t)S_ * S_);

    // 6. causal-limited softmax -> split fp16 P
    softmax_split<<<B_ * S_, 256>>>(Sc, Ph, Pl);

    // 7. out = P V  (K limited to rowBase+128)
    hmma_gemm<0, false, true><<<dim3(D_ / 128, S_ / 128, B_), 256, SMEM_BYTES>>>(
        Ph, Pl, Vth, out, nullptr, nullptr, D_, S_,
        (size_t)S_ * S_, (size_t)D_ * S_, (size_t)S_ * D_);
}

// round 11
// speedup vs baseline: 1.4153x; 1.3164x over previous
#include <cuda_runtime.h>
#include <cuda_fp16.h>
#include <cstdint>

// CausalAttention B=8, S=2048, D=1024 fp32 via fp16 mma.sync GEMMs.
// Precision plan (validated by R8/R10 calibration):
//   projections: Q/K/V = cast16(x) @ cast16(W)    (1-term, 1 mma per k-slice)
//   QK: (Qh+Ql) @ Kh^T   (A-side 2-term; Q stored exact-to-22-bits)
//   PV: (Ph+Pl) @ Vt^T   (A-side 2-term)
// R11 = R8 minus xl in projections: 86M -> 61M mma instructions.

constexpr int B_ = 8;
constexpr int S_ = 2048;
constexpr int D_ = 1024;
constexpr int MTOT = B_ * S_;          // 16384

// ---------------- scratch (device globals; allocation-free) ----------------
__device__ __half g_xh[MTOT * D_];
__device__ __half g_Wth[3][D_ * D_];                     // W^T hi only [3][D,D]
__device__ __half g_Qh[MTOT * D_], g_Ql[MTOT * D_];      // Q 2-term (A side)
__device__ __half g_Kh[MTOT * D_];                       // K hi only (B side)
__device__ __half g_Vh[MTOT * D_];                       // V hi only
__device__ __half g_Vth[MTOT * D_];                      // V^T hi [B][D][S]
__device__ float  g_Sc[(size_t)B_ * S_ * S_];
__device__ __half g_Ph[(size_t)B_ * S_ * S_], g_Pl[(size_t)B_ * S_ * S_];

// ---------------- helpers ----------------
__device__ __forceinline__ uint32_t smem_u32(const void* p) {
    uint32_t a;
    asm("{ .reg .u64 t; cvta.to.shared.u64 t, %1; cvt.u32.u64 %0, t; }"
        : "=r"(a) : "l"(p));
    return a;
}
__device__ __forceinline__ void cp_async16(uint32_t dst, const void* src) {
    asm volatile("cp.async.cg.shared.global [%0], [%1], 16;"
                 :: "r"(dst), "l"(__cvta_generic_to_global(src)) : "memory");
}
__device__ __forceinline__ void cp_commit() {
    asm volatile("cp.async.commit_group;" ::: "memory");
}
template <int N>
__device__ __forceinline__ void cp_wait() {
    asm volatile("cp.async.wait_group %0;" :: "n"(N) : "memory");
}
__device__ __forceinline__ void ldm_x4(uint32_t* r, uint32_t addr) {
    asm volatile("ldmatrix.sync.aligned.m8n8.x4.shared.b16 {%0,%1,%2,%3}, [%4];"
                 : "=r"(r[0]), "=r"(r[1]), "=r"(r[2]), "=r"(r[3]) : "r"(addr));
}
__device__ __forceinline__ void mma16816(float* c, const uint32_t* a,
                                         uint32_t b0, uint32_t b1) {
    asm("mma.sync.aligned.m16n8k16.row.col.f32.f16.f16.f32 "
        "{%0,%1,%2,%3}, {%4,%5,%6,%7}, {%8,%9}, {%0,%1,%2,%3};"
        : "+f"(c[0]), "+f"(c[1]), "+f"(c[2]), "+f"(c[3])
        : "r"(a[0]), "r"(a[1]), "r"(a[2]), "r"(a[3]), "r"(b0), "r"(b1));
}

// ---------------- cast / transpose / softmax kernels ----------------
__global__ __launch_bounds__(256)
void cast_f32h(const float* __restrict__ in, __half* __restrict__ h, int n4) {
    int i = blockIdx.x * 256 + threadIdx.x;
    if (i >= n4) return;
    float4 v = *reinterpret_cast<const float4*>(in + (size_t)i * 4);
    __half2 hp0 = __floats2half2_rn(v.x, v.y);
    __half2 hp1 = __floats2half2_rn(v.z, v.w);
    uint2 hu;
    hu.x = *reinterpret_cast<uint32_t*>(&hp0);
    hu.y = *reinterpret_cast<uint32_t*>(&hp1);
    *reinterpret_cast<uint2*>(h + (size_t)i * 4) = hu;
}

__global__ __launch_bounds__(256)
void transpose_h(const float* __restrict__ in, __half* __restrict__ oh, int R, int C) {
    __shared__ float t[32][33];
    int c0 = blockIdx.x * 32, r0 = blockIdx.y * 32;
    int tx = threadIdx.x;
#pragma unroll
    for (int j = 0; j < 4; j++) {
        int ty = threadIdx.y * 4 + j;
        t[ty][tx] = in[(size_t)(r0 + ty) * C + c0 + tx];
    }
    __syncthreads();
#pragma unroll
    for (int j = 0; j < 4; j++) {
        int ty = threadIdx.y * 4 + j;
        oh[(size_t)(c0 + ty) * R + r0 + tx] = __float2half_rn(t[tx][ty]);
    }
}

__global__ __launch_bounds__(256)
void transpose_half(const __half* __restrict__ ih, __half* __restrict__ oh) {
    __shared__ __half th[32][34];
    int z = blockIdx.z;
    ih += (size_t)z * S_ * D_;
    oh += (size_t)z * D_ * S_;
    int c0 = blockIdx.x * 32, r0 = blockIdx.y * 32;
    int tx = threadIdx.x;
#pragma unroll
    for (int j = 0; j < 4; j++) {
        int ty = threadIdx.y * 4 + j;
        th[ty][tx] = ih[(size_t)(r0 + ty) * D_ + c0 + tx];
    }
    __syncthreads();
#pragma unroll
    for (int j = 0; j < 4; j++) {
        int ty = threadIdx.y * 4 + j;
        oh[(size_t)(c0 + ty) * S_ + r0 + tx] = th[tx][ty];
    }
}

__global__ __launch_bounds__(256)
void softmax_split(const float* __restrict__ Sc, __half* __restrict__ Ph,
                   __half* __restrict__ Pl) {
    const int r = blockIdx.x, i = r % S_;
    const size_t off = (size_t)r * S_;
    const float* row = Sc + off;
    const int n = i + 1;
    const int nIt = (n + 255) >> 8;
    const int kLim = (n + 127) & ~127;
    const float scale = 0.03125f;                // 1/sqrt(1024)
    const int tid = threadIdx.x;

    float vals[8];
    float m = -INFINITY;
    for (int it = 0; it < nIt; it++) {
        int j = it * 256 + tid;
        float v = (j < n) ? row[j] * scale : -INFINITY;
        vals[it] = v; m = fmaxf(m, v);
    }
    __shared__ float red[8];
#pragma unroll
    for (int o = 16; o > 0; o >>= 1) m = fmaxf(m, __shfl_xor_sync(~0u, m, o));
    if ((tid & 31) == 0) red[tid >> 5] = m;
    __syncthreads();
    float M = red[0];
#pragma unroll
    for (int w = 1; w < 8; w++) M = fmaxf(M, red[w]);
    __syncthreads();
    float ssum = 0.f;
    for (int it = 0; it < nIt; it++) {
        int j = it * 256 + tid;
        float e = (j < n) ? __expf(vals[it] - M) : 0.f;
        vals[it] = e; ssum += e;
    }
#pragma unroll
    for (int o = 16; o > 0; o >>= 1) ssum += __shfl_xor_sync(~0u, ssum, o);
    if ((tid & 31) == 0) red[tid >> 5] = ssum;
    __syncthreads();
    float T = 0.f;
#pragma unroll
    for (int w = 0; w < 8; w++) T += red[w];
    const float inv = 1.f / T;
    for (int it = 0; it < nIt; it++) {
        int j = it * 256 + tid;
        if (j < kLim) {
            float v = (j < n) ? vals[it] * inv : 0.f;
            __half hv = __float2half_rn(v);
            Ph[off + j] = hv;
            Pl[off + j] = __float2half_rn(v - __half2float(hv));
        }
    }
}

// ---------------- fp16 HMMA GEMM, TERMS-parameterized ----------------
// C[M,N] = (Ah [+Al])[M,K] * Bh[N,K]^T, tile 128x128, BK=64, 8 warps (32x64).
// TERMS=1: single A tile, 1 mma per (mt,nt,ks). TERMS=2: hi+lo A, 2 mmas.
// EP: 0 -> fp32 to Cf;  1 -> fp16 hi+lo (Ch,Cl);  2 -> fp16 hi only (Ch).
constexpr int TILE_B = 16384;                    // one 128x64 fp16 tile

template <int EP, bool CSKIP, bool CLIMK, int TERMS>
__global__ __launch_bounds__(256, 2)
void hmma_gemm(const __half* __restrict__ Ah, const __half* __restrict__ Al,
               const __half* __restrict__ Bh,
               float* __restrict__ Cf, __half* __restrict__ Ch,
               __half* __restrict__ Cl,
               int N, int K, size_t sA, size_t sB, size_t sC)
{
    constexpr int STG = (TERMS + 1) * TILE_B;     // tiles per stage
    const int rowBase = blockIdx.y * 128, colBase = blockIdx.x * 128;
    if (CSKIP && colBase > rowBase) return;
    const int kEnd = CLIMK ? (rowBase + 128) : K;
    const int NC = kEnd >> 6;                     // chunks of 64 K

    extern __shared__ char smem[];
    const uint32_t sbase = smem_u32(smem);

    const size_t zA = (size_t)blockIdx.z * sA, zB = (size_t)blockIdx.z * sB;
    Ah += zA; Bh += zB;
    if (TERMS == 2) Al += zA;

    const int tid = threadIdx.x, wid = tid >> 5, lid = tid & 31;
    const int wr = wid & 3, wc = wid >> 2;         // warp grid 4(m) x 2(n)

    uint32_t aRel[2], aXor[2];
#pragma unroll
    for (int mt = 0; mt < 2; mt++) {
        int r = wr * 32 + mt * 16 + (lid & 15);
        aRel[mt] = r * 128;
        aXor[mt] = (r & 7) << 4;
    }
    const uint32_t aHalf = (lid >> 4) * 16;
    const int g = lid >> 3;
    uint32_t bRel[4], bXor[4];
#pragma unroll
    for (int nt = 0; nt < 4; nt++) {
        int r = wc * 64 + nt * 16 + ((g & 1) << 3) + (lid & 7);
        bRel[nt] = r * 128;
        bXor[nt] = (r & 7) << 4;
    }
    const uint32_t bHalf = (g >> 1) * 16;

    float acc[2][8][4];
#pragma unroll
    for (int i = 0; i < 2; i++)
#pragma unroll
        for (int j = 0; j < 8; j++)
#pragma unroll
            for (int k = 0; k < 4; k++) acc[i][j][k] = 0.f;

    auto loadChunk = [&](int c, int buf) {
        const int k0 = c << 6;
        const uint32_t st = sbase + buf * STG;
#pragma unroll
        for (int j = 0; j < 4; j++) {
            int idx = j * 256 + tid;                   // 0..1023
            int row = idx >> 3, col = idx & 7;         // 128 rows x 8 cols of 16B
            uint32_t off = row * 128 + ((col * 16) ^ ((row & 7) << 4));
            size_t ga = (size_t)(rowBase + row) * K + k0 + col * 8;
            size_t gb = (size_t)(colBase + row) * K + k0 + col * 8;
            cp_async16(st + off, Ah + ga);
            if (TERMS == 2) cp_async16(st + TILE_B + off, Al + ga);
            cp_async16(st + (TERMS == 2 ? 2 : 1) * TILE_B + off, Bh + gb);
        }
        cp_commit();
    };

    loadChunk(0, 0);

    for (int c = 0; c < NC; c++) {
        const int buf = c & 1;
        cp_wait<0>();
        __syncthreads();
        if (c + 1 < NC) loadChunk(c + 1, buf ^ 1);

        const uint32_t sAh = sbase + buf * STG;
        const uint32_t sAl = sAh + TILE_B;
        const uint32_t sBh = sAh + (TERMS == 2 ? 2 : 1) * TILE_B;
#pragma unroll
        for (int ks = 0; ks < 4; ks++) {
            const uint32_t kb = ks * 32;
            uint32_t ah[2][4], al[2][4], bh[4][4];
#pragma unroll
            for (int nt = 0; nt < 4; nt++)
                ldm_x4(bh[nt], sBh + bRel[nt] + ((kb + bHalf) ^ bXor[nt]));
#pragma unroll
            for (int mt = 0; mt < 2; mt++) {
                uint32_t o = aRel[mt] + ((kb + aHalf) ^ aXor[mt]);
                ldm_x4(ah[mt], sAh + o);
                if (TERMS == 2) ldm_x4(al[mt], sAl + o);
            }
            // hi group (16 independent acc quads)
#pragma unroll
            for (int mt = 0; mt < 2; mt++)
#pragma unroll
                for (int nt = 0; nt < 4; nt++) {
                    mma16816(acc[mt][2 * nt],     ah[mt], bh[nt][0], bh[nt][2]);
                    mma16816(acc[mt][2 * nt + 1], ah[mt], bh[nt][1], bh[nt][3]);
                }
            if (TERMS == 2) {
#pragma unroll
                for (int mt = 0; mt < 2; mt++)
#pragma unroll
                    for (int nt = 0; nt < 4; nt++) {
                        mma16816(acc[mt][2 * nt],     al[mt], bh[nt][0], bh[nt][2]);
                        mma16816(acc[mt][2 * nt + 1], al[mt], bh[nt][1], bh[nt][3]);
                    }
            }
        }
        __syncthreads();
    }

    // ---- epilogue ----
    const int colW = colBase + wc * 64 + (lid & 3) * 2;
#pragma unroll
    for (int mt = 0; mt < 2; mt++) {
        const int row0 = rowBase + wr * 32 + mt * 16 + (lid >> 2);
#pragma unroll
        for (int nt = 0; nt < 8; nt++) {
            const int col = colW + nt * 8;
            const float* cc = acc[mt][nt];
            if (EP == 0) {
                float* base = Cf + (size_t)blockIdx.z * sC;
                *reinterpret_cast<float2*>(base + (size_t)row0 * N + col) =
                    make_float2(cc[0], cc[1]);
                *reinterpret_cast<float2*>(base + (size_t)(row0 + 8) * N + col) =
                    make_float2(cc[2], cc[3]);
            } else {
#pragma unroll
                for (int h = 0; h < 2; h++) {
                    float f0 = cc[2 * h], f1 = cc[2 * h + 1];
                    __half h0 = __float2half_rn(f0), h1 = __float2half_rn(f1);
                    __half2 hp{h0, h1};
                    size_t o = (size_t)(row0 + h * 8) * N + col;
                    *reinterpret_cast<uint32_t*>(Ch + o) =
                        *reinterpret_cast<uint32_t*>(&hp);
                    if (EP == 1) {
                        __half2 lp = __floats2half2_rn(f0 - __half2float(h0),
                                                       f1 - __half2float(h1));
                        *reinterpret_cast<uint32_t*>(Cl + o) =
                            *reinterpret_cast<uint32_t*>(&lp);
                    }
                }
            }
        }
    }
}

// ---------------- launch ----------------
extern "C" void kernel_launch(void* const* d_in, const int* in_sizes, int n_in,
                              void* d_out, int out_size)
{
    const float* x  = (const float*)d_in[0];
    const float* Wq = (const float*)d_in[1];
    const float* Wk = (const float*)d_in[2];
    const float* Wv = (const float*)d_in[3];
    float* out = (float*)d_out;

    __half *xh, *Wth, *Qh, *Ql, *Kh, *Vh, *Vth, *Ph, *Pl;
    float *Sc;
    cudaGetSymbolAddress((void**)&xh, g_xh);
    cudaGetSymbolAddress((void**)&Wth, g_Wth);
    cudaGetSymbolAddress((void**)&Qh, g_Qh);   cudaGetSymbolAddress((void**)&Ql, g_Ql);
    cudaGetSymbolAddress((void**)&Kh, g_Kh);   cudaGetSymbolAddress((void**)&Vh, g_Vh);
    cudaGetSymbolAddress((void**)&Vth, g_Vth);
    cudaGetSymbolAddress((void**)&Sc, g_Sc);
    cudaGetSymbolAddress((void**)&Ph, g_Ph);   cudaGetSymbolAddress((void**)&Pl, g_Pl);

    constexpr int SMEM_1T = 2 * 2 * TILE_B;   // 64 KB (2 stages x 2 tiles)
    constexpr int SMEM_2T = 2 * 3 * TILE_B;   // 96 KB (2 stages x 3 tiles)

    cudaFuncSetAttribute(hmma_gemm<1, false, false, 1>,
                         cudaFuncAttributeMaxDynamicSharedMemorySize, SMEM_1T);
    cudaFuncSetAttribute(hmma_gemm<2, false, false, 1>,
                         cudaFuncAttributeMaxDynamicSharedMemorySize, SMEM_1T);
    cudaFuncSetAttribute(hmma_gemm<0, true, false, 2>,
                         cudaFuncAttributeMaxDynamicSharedMemorySize, SMEM_2T);
    cudaFuncSetAttribute(hmma_gemm<0, false, true, 2>,
                         cudaFuncAttributeMaxDynamicSharedMemorySize, SMEM_2T);

    // 1. cast x to fp16
    cast_f32h<<<(MTOT * D_ / 4 + 255) / 256, 256>>>(x, xh, MTOT * D_ / 4);
    // 2. transpose weights -> fp16 hi only [dout, din]
    dim3 tb(32, 8);
    transpose_h<<<dim3(32, 32, 1), tb>>>(Wq, Wth, D_, D_);
    transpose_h<<<dim3(32, 32, 1), tb>>>(Wk, Wth + (size_t)D_ * D_, D_, D_);
    transpose_h<<<dim3(32, 32, 1), tb>>>(Wv, Wth + 2 * (size_t)D_ * D_, D_, D_);

    // 3. projections (1-term x): Q -> hi+lo; K,V -> hi only
    dim3 gp(D_ / 128, MTOT / 128, 1);
    hmma_gemm<1, false, false, 1><<<gp, 256, SMEM_1T>>>(
        xh, nullptr, Wth, nullptr, Qh, Ql, D_, D_, 0, 0, 0);
    hmma_gemm<2, false, false, 1><<<gp, 256, SMEM_1T>>>(
        xh, nullptr, Wth + (size_t)D_ * D_, nullptr, Kh, nullptr, D_, D_, 0, 0, 0);
    hmma_gemm<2, false, false, 1><<<gp, 256, SMEM_1T>>>(
        xh, nullptr, Wth + 2 * (size_t)D_ * D_, nullptr, Vh, nullptr, D_, D_, 0, 0, 0);

    // 4. V -> Vt (fp16, per batch [S,D] -> [D,S])
    transpose_half<<<dim3(D_ / 32, S_ / 32, B_), tb>>>(Vh, Vth);

    // 5. scores = Q K^T (lower-triangular blocks), fp32, A-side 2-term
    hmma_gemm<0, true, false, 2><<<dim3(S_ / 128, S_ / 128, B_), 256, SMEM_2T>>>(
        Qh, Ql, Kh, Sc, nullptr, nullptr, S_, D_,
        (size_t)S_ * D_, (size_t)S_ * D_, (size_t)S_ * S_);

    // 6. causal-limited softmax -> split fp16 P
    softmax_split<<<B_ * S_, 256>>>(Sc, Ph, Pl);

    // 7. out = P V  (K limited to rowBase+128), A-side 2-term
    hmma_gemm<0, false, true, 2><<<dim3(D_ / 128, S_ / 128, B_), 256, SMEM_2T>>>(
        Ph, Pl, Vth, out, nullptr, nullptr, D_, S_,
        (size_t)S_ * S_, (size_t)D_ * S_, (size_t)S_ * D_);
}

// round 12
// speedup vs baseline: 1.6444x; 1.1619x over previous
#include <cuda_runtime.h>
#include <cuda_fp16.h>
#include <cstdint>

// CausalAttention B=8, S=2048, D=1024 fp32 via fp16 mma.sync GEMMs.
// Precision plan (calibrated R8/R10/R11):
//   projections: Q/K/V = cast16(x) @ cast16(W)    (1-term)
//   QK: (Qh+Ql) @ Kh^T   (A-side 2-term; Q exact to 22 bits)
//   PV:  Ph     @ Vt^T   (1-term; P in [0,1], rounding cancels over ~10^3 terms)
// R12 = R11 minus Pl: 61M -> 52.1M mma instructions.

constexpr int B_ = 8;
constexpr int S_ = 2048;
constexpr int D_ = 1024;
constexpr int MTOT = B_ * S_;          // 16384

// ---------------- scratch (device globals; allocation-free) ----------------
__device__ __half g_xh[MTOT * D_];
__device__ __half g_Wth[3][D_ * D_];                     // W^T hi only [3][D,D]
__device__ __half g_Qh[MTOT * D_], g_Ql[MTOT * D_];      // Q 2-term (A side)
__device__ __half g_Kh[MTOT * D_];                       // K hi only (B side)
__device__ __half g_Vh[MTOT * D_];                       // V hi only
__device__ __half g_Vth[MTOT * D_];                      // V^T hi [B][D][S]
__device__ float  g_Sc[(size_t)B_ * S_ * S_];
__device__ __half g_Ph[(size_t)B_ * S_ * S_];

// ---------------- helpers ----------------
__device__ __forceinline__ uint32_t smem_u32(const void* p) {
    uint32_t a;
    asm("{ .reg .u64 t; cvta.to.shared.u64 t, %1; cvt.u32.u64 %0, t; }"
        : "=r"(a) : "l"(p));
    return a;
}
__device__ __forceinline__ void cp_async16(uint32_t dst, const void* src) {
    asm volatile("cp.async.cg.shared.global [%0], [%1], 16;"
                 :: "r"(dst), "l"(__cvta_generic_to_global(src)) : "memory");
}
__device__ __forceinline__ void cp_commit() {
    asm volatile("cp.async.commit_group;" ::: "memory");
}
template <int N>
__device__ __forceinline__ void cp_wait() {
    asm volatile("cp.async.wait_group %0;" :: "n"(N) : "memory");
}
__device__ __forceinline__ void ldm_x4(uint32_t* r, uint32_t addr) {
    asm volatile("ldmatrix.sync.aligned.m8n8.x4.shared.b16 {%0,%1,%2,%3}, [%4];"
                 : "=r"(r[0]), "=r"(r[1]), "=r"(r[2]), "=r"(r[3]) : "r"(addr));
}
__device__ __forceinline__ void mma16816(float* c, const uint32_t* a,
                                         uint32_t b0, uint32_t b1) {
    asm("mma.sync.aligned.m16n8k16.row.col.f32.f16.f16.f32 "
        "{%0,%1,%2,%3}, {%4,%5,%6,%7}, {%8,%9}, {%0,%1,%2,%3};"
        : "+f"(c[0]), "+f"(c[1]), "+f"(c[2]), "+f"(c[3])
        : "r"(a[0]), "r"(a[1]), "r"(a[2]), "r"(a[3]), "r"(b0), "r"(b1));
}

// ---------------- cast / transpose / softmax kernels ----------------
__global__ __launch_bounds__(256)
void cast_f32h(const float* __restrict__ in, __half* __restrict__ h, int n4) {
    int i = blockIdx.x * 256 + threadIdx.x;
    if (i >= n4) return;
    float4 v = *reinterpret_cast<const float4*>(in + (size_t)i * 4);
    __half2 hp0 = __floats2half2_rn(v.x, v.y);
    __half2 hp1 = __floats2half2_rn(v.z, v.w);
    uint2 hu;
    hu.x = *reinterpret_cast<uint32_t*>(&hp0);
    hu.y = *reinterpret_cast<uint32_t*>(&hp1);
    *reinterpret_cast<uint2*>(h + (size_t)i * 4) = hu;
}

__global__ __launch_bounds__(256)
void transpose_h(const float* __restrict__ in, __half* __restrict__ oh, int R, int C) {
    __shared__ float t[32][33];
    int c0 = blockIdx.x * 32, r0 = blockIdx.y * 32;
    int tx = threadIdx.x;
#pragma unroll
    for (int j = 0; j < 4; j++) {
        int ty = threadIdx.y * 4 + j;
        t[ty][tx] = in[(size_t)(r0 + ty) * C + c0 + tx];
    }
    __syncthreads();
#pragma unroll
    for (int j = 0; j < 4; j++) {
        int ty = threadIdx.y * 4 + j;
        oh[(size_t)(c0 + ty) * R + r0 + tx] = __float2half_rn(t[tx][ty]);
    }
}

__global__ __launch_bounds__(256)
void transpose_half(const __half* __restrict__ ih, __half* __restrict__ oh) {
    __shared__ __half th[32][34];
    int z = blockIdx.z;
    ih += (size_t)z * S_ * D_;
    oh += (size_t)z * D_ * S_;
    int c0 = blockIdx.x * 32, r0 = blockIdx.y * 32;
    int tx = threadIdx.x;
#pragma unroll
    for (int j = 0; j < 4; j++) {
        int ty = threadIdx.y * 4 + j;
        th[ty][tx] = ih[(size_t)(r0 + ty) * D_ + c0 + tx];
    }
    __syncthreads();
#pragma unroll
    for (int j = 0; j < 4; j++) {
        int ty = threadIdx.y * 4 + j;
        oh[(size_t)(c0 + ty) * S_ + r0 + tx] = th[tx][ty];
    }
}

__global__ __launch_bounds__(256)
void softmax_h(const float* __restrict__ Sc, __half* __restrict__ Ph) {
    const int r = blockIdx.x, i = r % S_;
    const size_t off = (size_t)r * S_;
    const float* row = Sc + off;
    const int n = i + 1;
    const int nIt = (n + 255) >> 8;
    const int kLim = (n + 127) & ~127;
    const float scale = 0.03125f;                // 1/sqrt(1024)
    const int tid = threadIdx.x;

    float vals[8];
    float m = -INFINITY;
    for (int it = 0; it < nIt; it++) {
        int j = it * 256 + tid;
        float v = (j < n) ? row[j] * scale : -INFINITY;
        vals[it] = v; m = fmaxf(m, v);
    }
    __shared__ float red[8];
#pragma unroll
    for (int o = 16; o > 0; o >>= 1) m = fmaxf(m, __shfl_xor_sync(~0u, m, o));
    if ((tid & 31) == 0) red[tid >> 5] = m;
    __syncthreads();
    float M = red[0];
#pragma unroll
    for (int w = 1; w < 8; w++) M = fmaxf(M, red[w]);
    __syncthreads();
    float ssum = 0.f;
    for (int it = 0; it < nIt; it++) {
        int j = it * 256 + tid;
        float e = (j < n) ? __expf(vals[it] - M) : 0.f;
        vals[it] = e; ssum += e;
    }
#pragma unroll
    for (int o = 16; o > 0; o >>= 1) ssum += __shfl_xor_sync(~0u, ssum, o);
    if ((tid & 31) == 0) red[tid >> 5] = ssum;
    __syncthreads();
    float T = 0.f;
#pragma unroll
    for (int w = 0; w < 8; w++) T += red[w];
    const float inv = 1.f / T;
    for (int it = 0; it < nIt; it++) {
        int j = it * 256 + tid;
        if (j < kLim) {
            float v = (j < n) ? vals[it] * inv : 0.f;
            Ph[off + j] = __float2half_rn(v);
        }
    }
}

// ---------------- fp16 HMMA GEMM, TERMS-parameterized ----------------
// C[M,N] = (Ah [+Al])[M,K] * Bh[N,K]^T, tile 128x128, BK=64, 8 warps (32x64).
// TERMS=1: 1 mma per (mt,nt,ks). TERMS=2: hi+lo A, 2 mmas.
// EP: 0 -> fp32 to Cf;  1 -> fp16 hi+lo (Ch,Cl);  2 -> fp16 hi only (Ch).
constexpr int TILE_B = 16384;                    // one 128x64 fp16 tile

template <int EP, bool CSKIP, bool CLIMK, int TERMS>
__global__ __launch_bounds__(256, 2)
void hmma_gemm(const __half* __restrict__ Ah, const __half* __restrict__ Al,
               const __half* __restrict__ Bh,
               float* __restrict__ Cf, __half* __restrict__ Ch,
               __half* __restrict__ Cl,
               int N, int K, size_t sA, size_t sB, size_t sC)
{
    constexpr int STG = (TERMS + 1) * TILE_B;     // tiles per stage
    const int rowBase = blockIdx.y * 128, colBase = blockIdx.x * 128;
    if (CSKIP && colBase > rowBase) return;
    const int kEnd = CLIMK ? (rowBase + 128) : K;
    const int NC = kEnd >> 6;                     // chunks of 64 K

    extern __shared__ char smem[];
    const uint32_t sbase = smem_u32(smem);

    const size_t zA = (size_t)blockIdx.z * sA, zB = (size_t)blockIdx.z * sB;
    Ah += zA; Bh += zB;
    if (TERMS == 2) Al += zA;

    const int tid = threadIdx.x, wid = tid >> 5, lid = tid & 31;
    const int wr = wid & 3, wc = wid >> 2;         // warp grid 4(m) x 2(n)

    uint32_t aRel[2], aXor[2];
#pragma unroll
    for (int mt = 0; mt < 2; mt++) {
        int r = wr * 32 + mt * 16 + (lid & 15);
        aRel[mt] = r * 128;
        aXor[mt] = (r & 7) << 4;
    }
    const uint32_t aHalf = (lid >> 4) * 16;
    const int g = lid >> 3;
    uint32_t bRel[4], bXor[4];
#pragma unroll
    for (int nt = 0; nt < 4; nt++) {
        int r = wc * 64 + nt * 16 + ((g & 1) << 3) + (lid & 7);
        bRel[nt] = r * 128;
        bXor[nt] = (r & 7) << 4;
    }
    const uint32_t bHalf = (g >> 1) * 16;

    float acc[2][8][4];
#pragma unroll
    for (int i = 0; i < 2; i++)
#pragma unroll
        for (int j = 0; j < 8; j++)
#pragma unroll
            for (int k = 0; k < 4; k++) acc[i][j][k] = 0.f;

    auto loadChunk = [&](int c, int buf) {
        const int k0 = c << 6;
        const uint32_t st = sbase + buf * STG;
#pragma unroll
        for (int j = 0; j < 4; j++) {
            int idx = j * 256 + tid;                   // 0..1023
            int row = idx >> 3, col = idx & 7;         // 128 rows x 8 cols of 16B
            uint32_t off = row * 128 + ((col * 16) ^ ((row & 7) << 4));
            size_t ga = (size_t)(rowBase + row) * K + k0 + col * 8;
            size_t gb = (size_t)(colBase + row) * K + k0 + col * 8;
            cp_async16(st + off, Ah + ga);
            if (TERMS == 2) cp_async16(st + TILE_B + off, Al + ga);
            cp_async16(st + (TERMS == 2 ? 2 : 1) * TILE_B + off, Bh + gb);
        }
        cp_commit();
    };

    loadChunk(0, 0);

    for (int c = 0; c < NC; c++) {
        const int buf = c & 1;
        cp_wait<0>();
        __syncthreads();
        if (c + 1 < NC) loadChunk(c + 1, buf ^ 1);

        const uint32_t sAh = sbase + buf * STG;
        const uint32_t sAl = sAh + TILE_B;
        const uint32_t sBh = sAh + (TERMS == 2 ? 2 : 1) * TILE_B;
#pragma unroll
        for (int ks = 0; ks < 4; ks++) {
            const uint32_t kb = ks * 32;
            uint32_t ah[2][4], al[2][4], bh[4][4];
#pragma unroll
            for (int nt = 0; nt < 4; nt++)
                ldm_x4(bh[nt], sBh + bRel[nt] + ((kb + bHalf) ^ bXor[nt]));
#pragma unroll
            for (int mt = 0; mt < 2; mt++) {
                uint32_t o = aRel[mt] + ((kb + aHalf) ^ aXor[mt]);
                ldm_x4(ah[mt], sAh + o);
                if (TERMS == 2) ldm_x4(al[mt], sAl + o);
            }
#pragma unroll
            for (int mt = 0; mt < 2; mt++)
#pragma unroll
                for (int nt = 0; nt < 4; nt++) {
                    mma16816(acc[mt][2 * nt],     ah[mt], bh[nt][0], bh[nt][2]);
                    mma16816(acc[mt][2 * nt + 1], ah[mt], bh[nt][1], bh[nt][3]);
                }
            if (TERMS == 2) {
#pragma unroll
                for (int mt = 0; mt < 2; mt++)
#pragma unroll
                    for (int nt = 0; nt < 4; nt++) {
                        mma16816(acc[mt][2 * nt],     al[mt], bh[nt][0], bh[nt][2]);
                        mma16816(acc[mt][2 * nt + 1], al[mt], bh[nt][1], bh[nt][3]);
                    }
            }
        }
        __syncthreads();
    }

    // ---- epilogue ----
    const int colW = colBase + wc * 64 + (lid & 3) * 2;
#pragma unroll
    for (int mt = 0; mt < 2; mt++) {
        const int row0 = rowBase + wr * 32 + mt * 16 + (lid >> 2);
#pragma unroll
        for (int nt = 0; nt < 8; nt++) {
            const int col = colW + nt * 8;
            const float* cc = acc[mt][nt];
            if (EP == 0) {
                float* base = Cf + (size_t)blockIdx.z * sC;
                *reinterpret_cast<float2*>(base + (size_t)row0 * N + col) =
                    make_float2(cc[0], cc[1]);
                *reinterpret_cast<float2*>(base + (size_t)(row0 + 8) * N + col) =
                    make_float2(cc[2], cc[3]);
            } else {
#pragma unroll
                for (int h = 0; h < 2; h++) {
                    float f0 = cc[2 * h], f1 = cc[2 * h + 1];
                    __half h0 = __float2half_rn(f0), h1 = __float2half_rn(f1);
                    __half2 hp{h0, h1};
                    size_t o = (size_t)(row0 + h * 8) * N + col;
                    *reinterpret_cast<uint32_t*>(Ch + o) =
                        *reinterpret_cast<uint32_t*>(&hp);
                    if (EP == 1) {
                        __half2 lp = __floats2half2_rn(f0 - __half2float(h0),
                                                       f1 - __half2float(h1));
                        *reinterpret_cast<uint32_t*>(Cl + o) =
                            *reinterpret_cast<uint32_t*>(&lp);
                    }
                }
            }
        }
    }
}

// ---------------- launch ----------------
extern "C" void kernel_launch(void* const* d_in, const int* in_sizes, int n_in,
                              void* d_out, int out_size)
{
    const float* x  = (const float*)d_in[0];
    const float* Wq = (const float*)d_in[1];
    const float* Wk = (const float*)d_in[2];
    const float* Wv = (const float*)d_in[3];
    float* out = (float*)d_out;

    __half *xh, *Wth, *Qh, *Ql, *Kh, *Vh, *Vth, *Ph;
    float *Sc;
    cudaGetSymbolAddress((void**)&xh, g_xh);
    cudaGetSymbolAddress((void**)&Wth, g_Wth);
    cudaGetSymbolAddress((void**)&Qh, g_Qh);   cudaGetSymbolAddress((void**)&Ql, g_Ql);
    cudaGetSymbolAddress((void**)&Kh, g_Kh);   cudaGetSymbolAddress((void**)&Vh, g_Vh);
    cudaGetSymbolAddress((void**)&Vth, g_Vth);
    cudaGetSymbolAddress((void**)&Sc, g_Sc);
    cudaGetSymbolAddress((void**)&Ph, g_Ph);

    constexpr int SMEM_1T = 2 * 2 * TILE_B;   // 64 KB (2 stages x 2 tiles)
    constexpr int SMEM_2T = 2 * 3 * TILE_B;   // 96 KB (2 stages x 3 tiles)

    cudaFuncSetAttribute(hmma_gemm<1, false, false, 1>,
                         cudaFuncAttributeMaxDynamicSharedMemorySize, SMEM_1T);
    cudaFuncSetAttribute(hmma_gemm<2, false, false, 1>,
                         cudaFuncAttributeMaxDynamicSharedMemorySize, SMEM_1T);
    cudaFuncSetAttribute(hmma_gemm<0, true, false, 2>,
                         cudaFuncAttributeMaxDynamicSharedMemorySize, SMEM_2T);
    cudaFuncSetAttribute(hmma_gemm<0, false, true, 1>,
                         cudaFuncAttributeMaxDynamicSharedMemorySize, SMEM_1T);

    // 1. cast x to fp16
    cast_f32h<<<(MTOT * D_ / 4 + 255) / 256, 256>>>(x, xh, MTOT * D_ / 4);
    // 2. transpose weights -> fp16 hi only [dout, din]
    dim3 tb(32, 8);
    transpose_h<<<dim3(32, 32, 1), tb>>>(Wq, Wth, D_, D_);
    transpose_h<<<dim3(32, 32, 1), tb>>>(Wk, Wth + (size_t)D_ * D_, D_, D_);
    transpose_h<<<dim3(32, 32, 1), tb>>>(Wv, Wth + 2 * (size_t)D_ * D_, D_, D_);

    // 3. projections (1-term x): Q -> hi+lo; K,V -> hi only
    dim3 gp(D_ / 128, MTOT / 128, 1);
    hmma_gemm<1, false, false, 1><<<gp, 256, SMEM_1T>>>(
        xh, nullptr, Wth, nullptr, Qh, Ql, D_, D_, 0, 0, 0);
    hmma_gemm<2, false, false, 1><<<gp, 256, SMEM_1T>>>(
        xh, nullptr, Wth + (size_t)D_ * D_, nullptr, Kh, nullptr, D_, D_, 0, 0, 0);
    hmma_gemm<2, false, false, 1><<<gp, 256, SMEM_1T>>>(
        xh, nullptr, Wth + 2 * (size_t)D_ * D_, nullptr, Vh, nullptr, D_, D_, 0, 0, 0);

    // 4. V -> Vt (fp16, per batch [S,D] -> [D,S])
    transpose_half<<<dim3(D_ / 32, S_ / 32, B_), tb>>>(Vh, Vth);

    // 5. scores = Q K^T (lower-triangular blocks), fp32, A-side 2-term
    hmma_gemm<0, true, false, 2><<<dim3(S_ / 128, S_ / 128, B_), 256, SMEM_2T>>>(
        Qh, Ql, Kh, Sc, nullptr, nullptr, S_, D_,
        (size_t)S_ * D_, (size_t)S_ * D_, (size_t)S_ * S_);

    // 6. causal-limited softmax -> fp16 P (hi only)
    softmax_h<<<B_ * S_, 256>>>(Sc, Ph);

    // 7. out = P V  (K limited to rowBase+128), 1-term
    hmma_gemm<0, false, true, 1><<<dim3(D_ / 128, S_ / 128, B_), 256, SMEM_1T>>>(
        Ph, nullptr, Vth, out, nullptr, nullptr, D_, S_,
        (size_t)S_ * S_, (size_t)D_ * S_, (size_t)S_ * D_);
}

// round 13
// speedup vs baseline: 1.9597x; 1.1917x over previous
#include <cuda_runtime.h>
#include <cuda_fp16.h>
#include <cstdint>

// CausalAttention B=8, S=2048, D=1024 fp32 via fp16 mma.sync GEMMs.
// Precision plan (calibrated R8..R12; all pathways ~2.8e-4, quadrature):
//   projections: Q/K/V = cast16(x) @ cast16(W)
//   QK: Qh @ Kh^T      (1-term)
//   PV: Ph @ Vt^T      (1-term)
// R13 = R12 minus Ql: 52.1M -> 43.2M mma instructions. All GEMMs hi-only.

constexpr int B_ = 8;
constexpr int S_ = 2048;
constexpr int D_ = 1024;
constexpr int MTOT = B_ * S_;          // 16384

// ---------------- scratch (device globals; allocation-free) ----------------
__device__ __half g_xh[MTOT * D_];
__device__ __half g_Wth[3][D_ * D_];                     // W^T [3][D,D] fp16
__device__ __half g_Qh[MTOT * D_];
__device__ __half g_Kh[MTOT * D_];
__device__ __half g_Vh[MTOT * D_];
__device__ __half g_Vth[MTOT * D_];                      // V^T [B][D][S]
__device__ float  g_Sc[(size_t)B_ * S_ * S_];
__device__ __half g_Ph[(size_t)B_ * S_ * S_];

// ---------------- helpers ----------------
__device__ __forceinline__ uint32_t smem_u32(const void* p) {
    uint32_t a;
    asm("{ .reg .u64 t; cvta.to.shared.u64 t, %1; cvt.u32.u64 %0, t; }"
        : "=r"(a) : "l"(p));
    return a;
}
__device__ __forceinline__ void cp_async16(uint32_t dst, const void* src) {
    asm volatile("cp.async.cg.shared.global [%0], [%1], 16;"
                 :: "r"(dst), "l"(__cvta_generic_to_global(src)) : "memory");
}
__device__ __forceinline__ void cp_commit() {
    asm volatile("cp.async.commit_group;" ::: "memory");
}
template <int N>
__device__ __forceinline__ void cp_wait() {
    asm volatile("cp.async.wait_group %0;" :: "n"(N) : "memory");
}
__device__ __forceinline__ void ldm_x4(uint32_t* r, uint32_t addr) {
    asm volatile("ldmatrix.sync.aligned.m8n8.x4.shared.b16 {%0,%1,%2,%3}, [%4];"
                 : "=r"(r[0]), "=r"(r[1]), "=r"(r[2]), "=r"(r[3]) : "r"(addr));
}
__device__ __forceinline__ void mma16816(float* c, const uint32_t* a,
                                         uint32_t b0, uint32_t b1) {
    asm("mma.sync.aligned.m16n8k16.row.col.f32.f16.f16.f32 "
        "{%0,%1,%2,%3}, {%4,%5,%6,%7}, {%8,%9}, {%0,%1,%2,%3};"
        : "+f"(c[0]), "+f"(c[1]), "+f"(c[2]), "+f"(c[3])
        : "r"(a[0]), "r"(a[1]), "r"(a[2]), "r"(a[3]), "r"(b0), "r"(b1));
}

// ---------------- cast / transpose / softmax kernels ----------------
__global__ __launch_bounds__(256)
void cast_f32h(const float* __restrict__ in, __half* __restrict__ h, int n4) {
    int i = blockIdx.x * 256 + threadIdx.x;
    if (i >= n4) return;
    float4 v = *reinterpret_cast<const float4*>(in + (size_t)i * 4);
    __half2 hp0 = __floats2half2_rn(v.x, v.y);
    __half2 hp1 = __floats2half2_rn(v.z, v.w);
    uint2 hu;
    hu.x = *reinterpret_cast<uint32_t*>(&hp0);
    hu.y = *reinterpret_cast<uint32_t*>(&hp1);
    *reinterpret_cast<uint2*>(h + (size_t)i * 4) = hu;
}

__global__ __launch_bounds__(256)
void transpose_h(const float* __restrict__ in, __half* __restrict__ oh, int R, int C) {
    __shared__ float t[32][33];
    int c0 = blockIdx.x * 32, r0 = blockIdx.y * 32;
    int tx = threadIdx.x;
#pragma unroll
    for (int j = 0; j < 4; j++) {
        int ty = threadIdx.y * 4 + j;
        t[ty][tx] = in[(size_t)(r0 + ty) * C + c0 + tx];
    }
    __syncthreads();
#pragma unroll
    for (int j = 0; j < 4; j++) {
        int ty = threadIdx.y * 4 + j;
        oh[(size_t)(c0 + ty) * R + r0 + tx] = __float2half_rn(t[tx][ty]);
    }
}

__global__ __launch_bounds__(256)
void transpose_half(const __half* __restrict__ ih, __half* __restrict__ oh) {
    __shared__ __half th[32][34];
    int z = blockIdx.z;
    ih += (size_t)z * S_ * D_;
    oh += (size_t)z * D_ * S_;
    int c0 = blockIdx.x * 32, r0 = blockIdx.y * 32;
    int tx = threadIdx.x;
#pragma unroll
    for (int j = 0; j < 4; j++) {
        int ty = threadIdx.y * 4 + j;
        th[ty][tx] = ih[(size_t)(r0 + ty) * D_ + c0 + tx];
    }
    __syncthreads();
#pragma unroll
    for (int j = 0; j < 4; j++) {
        int ty = threadIdx.y * 4 + j;
        oh[(size_t)(c0 + ty) * S_ + r0 + tx] = th[tx][ty];
    }
}

__global__ __launch_bounds__(256)
void softmax_h(const float* __restrict__ Sc, __half* __restrict__ Ph) {
    const int r = blockIdx.x, i = r % S_;
    const size_t off = (size_t)r * S_;
    const float* row = Sc + off;
    const int n = i + 1;
    const int nIt = (n + 255) >> 8;
    const int kLim = (n + 127) & ~127;
    const float scale = 0.03125f;                // 1/sqrt(1024)
    const int tid = threadIdx.x;

    float vals[8];
    float m = -INFINITY;
    for (int it = 0; it < nIt; it++) {
        int j = it * 256 + tid;
        float v = (j < n) ? row[j] * scale : -INFINITY;
        vals[it] = v; m = fmaxf(m, v);
    }
    __shared__ float red[8];
#pragma unroll
    for (int o = 16; o > 0; o >>= 1) m = fmaxf(m, __shfl_xor_sync(~0u, m, o));
    if ((tid & 31) == 0) red[tid >> 5] = m;
    __syncthreads();
    float M = red[0];
#pragma unroll
    for (int w = 1; w < 8; w++) M = fmaxf(M, red[w]);
    __syncthreads();
    float ssum = 0.f;
    for (int it = 0; it < nIt; it++) {
        int j = it * 256 + tid;
        float e = (j < n) ? __expf(vals[it] - M) : 0.f;
        vals[it] = e; ssum += e;
    }
#pragma unroll
    for (int o = 16; o > 0; o >>= 1) ssum += __shfl_xor_sync(~0u, ssum, o);
    if ((tid & 31) == 0) red[tid >> 5] = ssum;
    __syncthreads();
    float T = 0.f;
#pragma unroll
    for (int w = 0; w < 8; w++) T += red[w];
    const float inv = 1.f / T;
    for (int it = 0; it < nIt; it++) {
        int j = it * 256 + tid;
        if (j < kLim) {
            float v = (j < n) ? vals[it] * inv : 0.f;
            Ph[off + j] = __float2half_rn(v);
        }
    }
}

// ---------------- fp16 HMMA GEMM (1-term) ----------------
// C[M,N] = A[M,K] * B[N,K]^T, tile 128x128, BK=64, 8 warps (32x64 each).
// EP: 0 -> fp32 to Cf;  2 -> fp16 to Ch.
// CSKIP: skip blocks above causal diagonal.  CLIMK: kEnd = rowBase+128.
constexpr int TILE_B = 16384;                    // one 128x64 fp16 tile
constexpr int STG_BYTES = 2 * TILE_B;            // A,B = 32 KB per stage
constexpr int SMEM_BYTES = 2 * STG_BYTES;        // 64 KB

template <int EP, bool CSKIP, bool CLIMK>
__global__ __launch_bounds__(256, 2)
void hmma_gemm(const __half* __restrict__ Ah, const __half* __restrict__ Bh,
               float* __restrict__ Cf, __half* __restrict__ Ch,
               int N, int K, size_t sA, size_t sB, size_t sC)
{
    const int rowBase = blockIdx.y * 128, colBase = blockIdx.x * 128;
    if (CSKIP && colBase > rowBase) return;
    const int kEnd = CLIMK ? (rowBase + 128) : K;
    const int NC = kEnd >> 6;                     // chunks of 64 K

    extern __shared__ char smem[];
    const uint32_t sbase = smem_u32(smem);

    Ah += (size_t)blockIdx.z * sA;
    Bh += (size_t)blockIdx.z * sB;

    const int tid = threadIdx.x, wid = tid >> 5, lid = tid & 31;
    const int wr = wid & 3, wc = wid >> 2;         // warp grid 4(m) x 2(n)

    uint32_t aRel[2], aXor[2];
#pragma unroll
    for (int mt = 0; mt < 2; mt++) {
        int r = wr * 32 + mt * 16 + (lid & 15);
        aRel[mt] = r * 128;
        aXor[mt] = (r & 7) << 4;
    }
    const uint32_t aHalf = (lid >> 4) * 16;
    const int g = lid >> 3;
    uint32_t bRel[4], bXor[4];
#pragma unroll
    for (int nt = 0; nt < 4; nt++) {
        int r = wc * 64 + nt * 16 + ((g & 1) << 3) + (lid & 7);
        bRel[nt] = r * 128;
        bXor[nt] = (r & 7) << 4;
    }
    const uint32_t bHalf = (g >> 1) * 16;

    float acc[2][8][4];
#pragma unroll
    for (int i = 0; i < 2; i++)
#pragma unroll
        for (int j = 0; j < 8; j++)
#pragma unroll
            for (int k = 0; k < 4; k++) acc[i][j][k] = 0.f;

    auto loadChunk = [&](int c, int buf) {
        const int k0 = c << 6;
        const uint32_t st = sbase + buf * STG_BYTES;
#pragma unroll
        for (int j = 0; j < 4; j++) {
            int idx = j * 256 + tid;                   // 0..1023
            int row = idx >> 3, col = idx & 7;         // 128 rows x 8 cols of 16B
            uint32_t off = row * 128 + ((col * 16) ^ ((row & 7) << 4));
            cp_async16(st + off, Ah + (size_t)(rowBase + row) * K + k0 + col * 8);
            cp_async16(st + TILE_B + off,
                       Bh + (size_t)(colBase + row) * K + k0 + col * 8);
        }
        cp_commit();
    };

    loadChunk(0, 0);

    for (int c = 0; c < NC; c++) {
        const int buf = c & 1;
        cp_wait<0>();
        __syncthreads();
        if (c + 1 < NC) loadChunk(c + 1, buf ^ 1);

        const uint32_t sAh = sbase + buf * STG_BYTES;
        const uint32_t sBh = sAh + TILE_B;
#pragma unroll
        for (int ks = 0; ks < 4; ks++) {
            const uint32_t kb = ks * 32;
            uint32_t ah[2][4], bh[4][4];
#pragma unroll
            for (int nt = 0; nt < 4; nt++)
                ldm_x4(bh[nt], sBh + bRel[nt] + ((kb + bHalf) ^ bXor[nt]));
#pragma unroll
            for (int mt = 0; mt < 2; mt++)
                ldm_x4(ah[mt], sAh + aRel[mt] + ((kb + aHalf) ^ aXor[mt]));
#pragma unroll
            for (int mt = 0; mt < 2; mt++)
#pragma unroll
                for (int nt = 0; nt < 4; nt++) {
                    mma16816(acc[mt][2 * nt],     ah[mt], bh[nt][0], bh[nt][2]);
                    mma16816(acc[mt][2 * nt + 1], ah[mt], bh[nt][1], bh[nt][3]);
                }
        }
        __syncthreads();
    }

    // ---- epilogue ----
    const int colW = colBase + wc * 64 + (lid & 3) * 2;
#pragma unroll
    for (int mt = 0; mt < 2; mt++) {
        const int row0 = rowBase + wr * 32 + mt * 16 + (lid >> 2);
#pragma unroll
        for (int nt = 0; nt < 8; nt++) {
            const int col = colW + nt * 8;
            const float* cc = acc[mt][nt];
            if (EP == 0) {
                float* base = Cf + (size_t)blockIdx.z * sC;
                *reinterpret_cast<float2*>(base + (size_t)row0 * N + col) =
                    make_float2(cc[0], cc[1]);
                *reinterpret_cast<float2*>(base + (size_t)(row0 + 8) * N + col) =
                    make_float2(cc[2], cc[3]);
            } else {
#pragma unroll
                for (int h = 0; h < 2; h++) {
                    __half2 hp = __floats2half2_rn(cc[2 * h], cc[2 * h + 1]);
                    size_t o = (size_t)(row0 + h * 8) * N + col;
                    *reinterpret_cast<uint32_t*>(Ch + o) =
                        *reinterpret_cast<uint32_t*>(&hp);
                }
            }
        }
    }
}

// ---------------- launch ----------------
extern "C" void kernel_launch(void* const* d_in, const int* in_sizes, int n_in,
                              void* d_out, int out_size)
{
    const float* x  = (const float*)d_in[0];
    const float* Wq = (const float*)d_in[1];
    const float* Wk = (const float*)d_in[2];
    const float* Wv = (const float*)d_in[3];
    float* out = (float*)d_out;

    __half *xh, *Wth, *Qh, *Kh, *Vh, *Vth, *Ph;
    float *Sc;
    cudaGetSymbolAddress((void**)&xh, g_xh);
    cudaGetSymbolAddress((void**)&Wth, g_Wth);
    cudaGetSymbolAddress((void**)&Qh, g_Qh);
    cudaGetSymbolAddress((void**)&Kh, g_Kh);
    cudaGetSymbolAddress((void**)&Vh, g_Vh);
    cudaGetSymbolAddress((void**)&Vth, g_Vth);
    cudaGetSymbolAddress((void**)&Sc, g_Sc);
    cudaGetSymbolAddress((void**)&Ph, g_Ph);

    cudaFuncSetAttribute(hmma_gemm<2, false, false>,
                         cudaFuncAttributeMaxDynamicSharedMemorySize, SMEM_BYTES);
    cudaFuncSetAttribute(hmma_gemm<0, true, false>,
                         cudaFuncAttributeMaxDynamicSharedMemorySize, SMEM_BYTES);
    cudaFuncSetAttribute(hmma_gemm<0, false, true>,
                         cudaFuncAttributeMaxDynamicSharedMemorySize, SMEM_BYTES);

    // 1. cast x to fp16
    cast_f32h<<<(MTOT * D_ / 4 + 255) / 256, 256>>>(x, xh, MTOT * D_ / 4);
    // 2. transpose weights -> fp16 [dout, din]
    dim3 tb(32, 8);
    transpose_h<<<dim3(32, 32, 1), tb>>>(Wq, Wth, D_, D_);
    transpose_h<<<dim3(32, 32, 1), tb>>>(Wk, Wth + (size_t)D_ * D_, D_, D_);
    transpose_h<<<dim3(32, 32, 1), tb>>>(Wv, Wth + 2 * (size_t)D_ * D_, D_, D_);

    // 3. projections (all fp16 hi-only)
    dim3 gp(D_ / 128, MTOT / 128, 1);
    hmma_gemm<2, false, false><<<gp, 256, SMEM_BYTES>>>(
        xh, Wth, nullptr, Qh, D_, D_, 0, 0, 0);
    hmma_gemm<2, false, false><<<gp, 256, SMEM_BYTES>>>(
        xh, Wth + (size_t)D_ * D_, nullptr, Kh, D_, D_, 0, 0, 0);
    hmma_gemm<2, false, false><<<gp, 256, SMEM_BYTES>>>(
        xh, Wth + 2 * (size_t)D_ * D_, nullptr, Vh, D_, D_, 0, 0, 0);

    // 4. V -> Vt (fp16, per batch [S,D] -> [D,S])
    transpose_half<<<dim3(D_ / 32, S_ / 32, B_), tb>>>(Vh, Vth);

    // 5. scores = Q K^T (lower-triangular blocks), fp32
    hmma_gemm<0, true, false><<<dim3(S_ / 128, S_ / 128, B_), 256, SMEM_BYTES>>>(
        Qh, Kh, Sc, nullptr, S_, D_,
        (size_t)S_ * D_, (size_t)S_ * D_, (size_t)S_ * S_);

    // 6. causal-limited softmax -> fp16 P
    softmax_h<<<B_ * S_, 256>>>(Sc, Ph);

    // 7. out = P V  (K limited to rowBase+128)
    hmma_gemm<0, false, true><<<dim3(D_ / 128, S_ / 128, B_), 256, SMEM_BYTES>>>(
        Ph, Vth, out, nullptr, D_, S_,
        (size_t)S_ * S_, (size_t)D_ * S_, (size_t)S_ * D_);
}

// round 14
// speedup vs baseline: 2.0042x; 1.0227x over previous
#include <cuda_runtime.h>
#include <cuda_fp16.h>
#include <cstdint>

// CausalAttention B=8, S=2048, D=1024 fp32 via fp16 mma.sync GEMMs.
//   projections: Q/K/V = cast16(x) @ cast16(W)
//   QK: Qh @ Kh^T      (B n-major, ldmatrix non-trans)
//   PV: Ph @ Vh        (B k-major [S,D], ldmatrix.trans — no V transpose)
// R14 = R13 minus transpose_half (+64MB traffic, +1 launch) and merged
//       weight transposes. Same arithmetic -> same rel_err.

constexpr int B_ = 8;
constexpr int S_ = 2048;
constexpr int D_ = 1024;
constexpr int MTOT = B_ * S_;          // 16384

// ---------------- scratch (device globals; allocation-free) ----------------
__device__ __half g_xh[MTOT * D_];
__device__ __half g_Wth[3][D_ * D_];                     // W^T [3][D,D] fp16
__device__ __half g_Qh[MTOT * D_];
__device__ __half g_Kh[MTOT * D_];
__device__ __half g_Vh[MTOT * D_];                       // V [B][S,D] natural
__device__ float  g_Sc[(size_t)B_ * S_ * S_];
__device__ __half g_Ph[(size_t)B_ * S_ * S_];

// ---------------- helpers ----------------
__device__ __forceinline__ uint32_t smem_u32(const void* p) {
    uint32_t a;
    asm("{ .reg .u64 t; cvta.to.shared.u64 t, %1; cvt.u32.u64 %0, t; }"
        : "=r"(a) : "l"(p));
    return a;
}
__device__ __forceinline__ void cp_async16(uint32_t dst, const void* src) {
    asm volatile("cp.async.cg.shared.global [%0], [%1], 16;"
                 :: "r"(dst), "l"(__cvta_generic_to_global(src)) : "memory");
}
__device__ __forceinline__ void cp_commit() {
    asm volatile("cp.async.commit_group;" ::: "memory");
}
template <int N>
__device__ __forceinline__ void cp_wait() {
    asm volatile("cp.async.wait_group %0;" :: "n"(N) : "memory");
}
__device__ __forceinline__ void ldm_x4(uint32_t* r, uint32_t addr) {
    asm volatile("ldmatrix.sync.aligned.m8n8.x4.shared.b16 {%0,%1,%2,%3}, [%4];"
                 : "=r"(r[0]), "=r"(r[1]), "=r"(r[2]), "=r"(r[3]) : "r"(addr));
}
__device__ __forceinline__ void ldm_x4t(uint32_t* r, uint32_t addr) {
    asm volatile("ldmatrix.sync.aligned.m8n8.x4.trans.shared.b16 {%0,%1,%2,%3}, [%4];"
                 : "=r"(r[0]), "=r"(r[1]), "=r"(r[2]), "=r"(r[3]) : "r"(addr));
}
__device__ __forceinline__ void mma16816(float* c, const uint32_t* a,
                                         uint32_t b0, uint32_t b1) {
    asm("mma.sync.aligned.m16n8k16.row.col.f32.f16.f16.f32 "
        "{%0,%1,%2,%3}, {%4,%5,%6,%7}, {%8,%9}, {%0,%1,%2,%3};"
        : "+f"(c[0]), "+f"(c[1]), "+f"(c[2]), "+f"(c[3])
        : "r"(a[0]), "r"(a[1]), "r"(a[2]), "r"(a[3]), "r"(b0), "r"(b1));
}

// ---------------- cast / transpose / softmax kernels ----------------
__global__ __launch_bounds__(256)
void cast_f32h(const float* __restrict__ in, __half* __restrict__ h, int n4) {
    int i = blockIdx.x * 256 + threadIdx.x;
    if (i >= n4) return;
    float4 v = *reinterpret_cast<const float4*>(in + (size_t)i * 4);
    __half2 hp0 = __floats2half2_rn(v.x, v.y);
    __half2 hp1 = __floats2half2_rn(v.z, v.w);
    uint2 hu;
    hu.x = *reinterpret_cast<uint32_t*>(&hp0);
    hu.y = *reinterpret_cast<uint32_t*>(&hp1);
    *reinterpret_cast<uint2*>(h + (size_t)i * 4) = hu;
}

// all 3 weights in one launch: z selects source
__global__ __launch_bounds__(256)
void transpose_w3(const float* __restrict__ w0, const float* __restrict__ w1,
                  const float* __restrict__ w2, __half* __restrict__ oh) {
    __shared__ float t[32][33];
    const float* in = (blockIdx.z == 0) ? w0 : (blockIdx.z == 1) ? w1 : w2;
    oh += (size_t)blockIdx.z * D_ * D_;
    int c0 = blockIdx.x * 32, r0 = blockIdx.y * 32;
    int tx = threadIdx.x;
#pragma unroll
    for (int j = 0; j < 4; j++) {
        int ty = threadIdx.y * 4 + j;
        t[ty][tx] = in[(size_t)(r0 + ty) * D_ + c0 + tx];
    }
    __syncthreads();
#pragma unroll
    for (int j = 0; j < 4; j++) {
        int ty = threadIdx.y * 4 + j;
        oh[(size_t)(c0 + ty) * D_ + r0 + tx] = __float2half_rn(t[tx][ty]);
    }
}

__global__ __launch_bounds__(256)
void softmax_h(const float* __restrict__ Sc, __half* __restrict__ Ph) {
    const int r = blockIdx.x, i = r % S_;
    const size_t off = (size_t)r * S_;
    const float* row = Sc + off;
    const int n = i + 1;
    const int nIt = (n + 255) >> 8;
    const int kLim = (n + 127) & ~127;
    const float scale = 0.03125f;                // 1/sqrt(1024)
    const int tid = threadIdx.x;

    float vals[8];
    float m = -INFINITY;
    for (int it = 0; it < nIt; it++) {
        int j = it * 256 + tid;
        float v = (j < n) ? row[j] * scale : -INFINITY;
        vals[it] = v; m = fmaxf(m, v);
    }
    __shared__ float red[8];
#pragma unroll
    for (int o = 16; o > 0; o >>= 1) m = fmaxf(m, __shfl_xor_sync(~0u, m, o));
    if ((tid & 31) == 0) red[tid >> 5] = m;
    __syncthreads();
    float M = red[0];
#pragma unroll
    for (int w = 1; w < 8; w++) M = fmaxf(M, red[w]);
    __syncthreads();
    float ssum = 0.f;
    for (int it = 0; it < nIt; it++) {
        int j = it * 256 + tid;
        float e = (j < n) ? __expf(vals[it] - M) : 0.f;
        vals[it] = e; ssum += e;
    }
#pragma unroll
    for (int o = 16; o > 0; o >>= 1) ssum += __shfl_xor_sync(~0u, ssum, o);
    if ((tid & 31) == 0) red[tid >> 5] = ssum;
    __syncthreads();
    float T = 0.f;
#pragma unroll
    for (int w = 0; w < 8; w++) T += red[w];
    const float inv = 1.f / T;
    for (int it = 0; it < nIt; it++) {
        int j = it * 256 + tid;
        if (j < kLim) {
            float v = (j < n) ? vals[it] * inv : 0.f;
            Ph[off + j] = __float2half_rn(v);
        }
    }
}

// ---------------- fp16 HMMA GEMM ----------------
// BTRANS=0: C = A[M,K] * B[N,K]^T  (B n-major, 128B rows, ldmatrix)
// BTRANS=1: C = A[M,K] * B[K,N]    (B k-major, 256B rows, ldmatrix.trans;
//                                    B global stride = N)
// tile 128x128, BK=64, 8 warps (32x64). EP: 0 -> fp32 Cf; 2 -> fp16 Ch.
// CSKIP: skip blocks above causal diagonal.  CLIMK: kEnd = rowBase+128.
constexpr int TILE_B = 16384;                    // one 16 KB operand tile
constexpr int STG_BYTES = 2 * TILE_B;            // A,B = 32 KB per stage
constexpr int SMEM_BYTES = 2 * STG_BYTES;        // 64 KB

template <int EP, bool CSKIP, bool CLIMK, bool BTRANS>
__global__ __launch_bounds__(256, 2)
void hmma_gemm(const __half* __restrict__ Ah, const __half* __restrict__ Bh,
               float* __restrict__ Cf, __half* __restrict__ Ch,
               int N, int K, size_t sA, size_t sB, size_t sC)
{
    const int rowBase = blockIdx.y * 128, colBase = blockIdx.x * 128;
    if (CSKIP && colBase > rowBase) return;
    const int kEnd = CLIMK ? (rowBase + 128) : K;
    const int NC = kEnd >> 6;                     // chunks of 64 K

    extern __shared__ char smem[];
    const uint32_t sbase = smem_u32(smem);

    Ah += (size_t)blockIdx.z * sA;
    Bh += (size_t)blockIdx.z * sB;

    const int tid = threadIdx.x, wid = tid >> 5, lid = tid & 31;
    const int wr = wid & 3, wc = wid >> 2;         // warp grid 4(m) x 2(n)

    // A fragments (row-major, 128B rows)
    uint32_t aRel[2], aXor[2];
#pragma unroll
    for (int mt = 0; mt < 2; mt++) {
        int r = wr * 32 + mt * 16 + (lid & 15);
        aRel[mt] = r * 128;
        aXor[mt] = (r & 7) << 4;
    }
    const uint32_t aHalf = (lid >> 4) * 16;

    // B fragments
    const int g = lid >> 3;
    uint32_t bRel[4], bXor[4];       // BTRANS=0 path
    uint32_t vRel[4];                // BTRANS=1 path (per-ks add = 4096)
    if (!BTRANS) {
#pragma unroll
        for (int nt = 0; nt < 4; nt++) {
            int r = wc * 64 + nt * 16 + ((g & 1) << 3) + (lid & 7);
            bRel[nt] = r * 128;
            bXor[nt] = (r & 7) << 4;
        }
    } else {
        // lanes: m = lid>>3; krow = (m>>1)*8 + (lid&7); ncol = (m&1)*8
        const int kLane = ((lid >> 4) << 3) + (lid & 7);
        const uint32_t lXor = (uint32_t)(lid & 7) << 4;
#pragma unroll
        for (int nt = 0; nt < 4; nt++) {
            uint32_t nByte = (uint32_t)(wc * 64 + nt * 16 + ((g & 1) << 3)) * 2;
            vRel[nt] = kLane * 256 + (nByte ^ lXor);
        }
    }
    const uint32_t bHalf = (g >> 1) * 16;         // BTRANS=0 only

    float acc[2][8][4];
#pragma unroll
    for (int i = 0; i < 2; i++)
#pragma unroll
        for (int j = 0; j < 8; j++)
#pragma unroll
            for (int k = 0; k < 4; k++) acc[i][j][k] = 0.f;

    auto loadChunk = [&](int c, int buf) {
        const int k0 = c << 6;
        const uint32_t st = sbase + buf * STG_BYTES;
#pragma unroll
        for (int j = 0; j < 4; j++) {
            int idx = j * 256 + tid;                   // 0..1023 granules
            {   // A tile: 128 rows x 64 k (128B rows)
                int row = idx >> 3, col = idx & 7;
                uint32_t off = row * 128 + ((col * 16) ^ ((row & 7) << 4));
                cp_async16(st + off, Ah + (size_t)(rowBase + row) * K + k0 + col * 8);
            }
            if (!BTRANS) {   // B tile: 128 n-rows x 64 k (128B rows)
                int row = idx >> 3, col = idx & 7;
                uint32_t off = row * 128 + ((col * 16) ^ ((row & 7) << 4));
                cp_async16(st + TILE_B + off,
                           Bh + (size_t)(colBase + row) * K + k0 + col * 8);
            } else {         // B tile: 64 k-rows x 128 n (256B rows)
                int row = idx >> 4, col = idx & 15;
                uint32_t off = row * 256 + ((col * 16) ^ ((row & 7) << 4));
                cp_async16(st + TILE_B + off,
                           Bh + (size_t)(k0 + row) * N + colBase + col * 8);
            }
        }
        cp_commit();
    };

    loadChunk(0, 0);

    for (int c = 0; c < NC; c++) {
        const int buf = c & 1;
        cp_wait<0>();
        __syncthreads();
        if (c + 1 < NC) loadChunk(c + 1, buf ^ 1);

        const uint32_t sAh = sbase + buf * STG_BYTES;
        const uint32_t sBh = sAh + TILE_B;
#pragma unroll
        for (int ks = 0; ks < 4; ks++) {
            const uint32_t kb = ks * 32;
            uint32_t ah[2][4], bh[4][4];
#pragma unroll
            for (int nt = 0; nt < 4; nt++) {
                if (!BTRANS)
                    ldm_x4(bh[nt], sBh + bRel[nt] + ((kb + bHalf) ^ bXor[nt]));
                else
                    ldm_x4t(bh[nt], sBh + ks * 4096 + vRel[nt]);
            }
#pragma unroll
            for (int mt = 0; mt < 2; mt++)
                ldm_x4(ah[mt], sAh + aRel[mt] + ((kb + aHalf) ^ aXor[mt]));
#pragma unroll
            for (int mt = 0; mt < 2; mt++)
#pragma unroll
                for (int nt = 0; nt < 4; nt++) {
                    mma16816(acc[mt][2 * nt],     ah[mt], bh[nt][0], bh[nt][2]);
                    mma16816(acc[mt][2 * nt + 1], ah[mt], bh[nt][1], bh[nt][3]);
                }
        }
        __syncthreads();
    }

    // ---- epilogue ----
    const int colW = colBase + wc * 64 + (lid & 3) * 2;
#pragma unroll
    for (int mt = 0; mt < 2; mt++) {
        const int row0 = rowBase + wr * 32 + mt * 16 + (lid >> 2);
#pragma unroll
        for (int nt = 0; nt < 8; nt++) {
            const int col = colW + nt * 8;
            const float* cc = acc[mt][nt];
            if (EP == 0) {
                float* base = Cf + (size_t)blockIdx.z * sC;
                *reinterpret_cast<float2*>(base + (size_t)row0 * N + col) =
                    make_float2(cc[0], cc[1]);
                *reinterpret_cast<float2*>(base + (size_t)(row0 + 8) * N + col) =
                    make_float2(cc[2], cc[3]);
            } else {
#pragma unroll
                for (int h = 0; h < 2; h++) {
                    __half2 hp = __floats2half2_rn(cc[2 * h], cc[2 * h + 1]);
                    size_t o = (size_t)(row0 + h * 8) * N + col;
                    *reinterpret_cast<uint32_t*>(Ch + o) =
                        *reinterpret_cast<uint32_t*>(&hp);
                }
            }
        }
    }
}

// ---------------- launch ----------------
extern "C" void kernel_launch(void* const* d_in, const int* in_sizes, int n_in,
                              void* d_out, int out_size)
{
    const float* x  = (const float*)d_in[0];
    const float* Wq = (const float*)d_in[1];
    const float* Wk = (const float*)d_in[2];
    const float* Wv = (const float*)d_in[3];
    float* out = (float*)d_out;

    __half *xh, *Wth, *Qh, *Kh, *Vh, *Ph;
    float *Sc;
    cudaGetSymbolAddress((void**)&xh, g_xh);
    cudaGetSymbolAddress((void**)&Wth, g_Wth);
    cudaGetSymbolAddress((void**)&Qh, g_Qh);
    cudaGetSymbolAddress((void**)&Kh, g_Kh);
    cudaGetSymbolAddress((void**)&Vh, g_Vh);
    cudaGetSymbolAddress((void**)&Sc, g_Sc);
    cudaGetSymbolAddress((void**)&Ph, g_Ph);

    cudaFuncSetAttribute(hmma_gemm<2, false, false, false>,
                         cudaFuncAttributeMaxDynamicSharedMemorySize, SMEM_BYTES);
    cudaFuncSetAttribute(hmma_gemm<0, true, false, false>,
                         cudaFuncAttributeMaxDynamicSharedMemorySize, SMEM_BYTES);
    cudaFuncSetAttribute(hmma_gemm<0, false, true, true>,
                         cudaFuncAttributeMaxDynamicSharedMemorySize, SMEM_BYTES);

    // 1. cast x to fp16
    cast_f32h<<<(MTOT * D_ / 4 + 255) / 256, 256>>>(x, xh, MTOT * D_ / 4);
    // 2. transpose all 3 weights (one launch) -> fp16 [dout, din]
    transpose_w3<<<dim3(32, 32, 3), dim3(32, 8)>>>(Wq, Wk, Wv, Wth);

    // 3. projections (fp16)
    dim3 gp(D_ / 128, MTOT / 128, 1);
    hmma_gemm<2, false, false, false><<<gp, 256, SMEM_BYTES>>>(
        xh, Wth, nullptr, Qh, D_, D_, 0, 0, 0);
    hmma_gemm<2, false, false, false><<<gp, 256, SMEM_BYTES>>>(
        xh, Wth + (size_t)D_ * D_, nullptr, Kh, D_, D_, 0, 0, 0);
    hmma_gemm<2, false, false, false><<<gp, 256, SMEM_BYTES>>>(
        xh, Wth + 2 * (size_t)D_ * D_, nullptr, Vh, D_, D_, 0, 0, 0);

    // 4. scores = Q K^T (lower-triangular blocks), fp32
    hmma_gemm<0, true, false, false><<<dim3(S_ / 128, S_ / 128, B_), 256, SMEM_BYTES>>>(
        Qh, Kh, Sc, nullptr, S_, D_,
        (size_t)S_ * D_, (size_t)S_ * D_, (size_t)S_ * S_);

    // 5. causal-limited softmax -> fp16 P
    softmax_h<<<B_ * S_, 256>>>(Sc, Ph);

    // 6. out = P V  (V in natural [S,D] layout via ldmatrix.trans)
    hmma_gemm<0, false, true, true><<<dim3(D_ / 128, S_ / 128, B_), 256, SMEM_BYTES>>>(
        Ph, Vh, out, nullptr, D_, S_,
        (size_t)S_ * S_, (size_t)S_ * D_, (size_t)S_ * D_);
}